// round 1
// baseline (speedup 1.0000x reference)
#include <cuda_runtime.h>
#include <math.h>

// Problem dims (fixed by reference): B=8192, D=H=1024, 4H=4096
#define BATCH 8192
#define HDIM  1024
#define GDIM  4096   // 4*H

// Scratch for the two pre-LN GEMM outputs (allocation-free rule: device globals)
__device__ float g_gh[(size_t)BATCH * GDIM];  // h0 @ Wh
__device__ float g_gx[(size_t)BATCH * GDIM];  // x  @ Wx

// ---------------------------------------------------------------------------
// Tiled SIMT fp32 GEMM: C[M,N] = A[M,K] @ B[K,N], row-major everything.
// 128x128 tile, BK=8, 256 threads, 8x8 per-thread microtile.
// which==0 -> write g_gh, which==1 -> write g_gx (avoids host symbol lookups).
// ---------------------------------------------------------------------------
#define BM 128
#define BN 128
#define BK 8
#define TM 8
#define TN 8

__global__ __launch_bounds__(256, 1)
void gemm_kernel(const float* __restrict__ A, const float* __restrict__ B,
                 int M, int N, int K, int which)
{
    float* __restrict__ C = which ? g_gx : g_gh;

    __shared__ float As[BK][BM];   // transposed A tile
    __shared__ float Bs[BK][BN];

    const int bx = blockIdx.x;     // N tile index
    const int by = blockIdx.y;     // M tile index
    const int tid = threadIdx.x;

    // A loading: 128 rows x 8 cols = 1024 floats = 256 float4 (1 per thread)
    const int arow = tid >> 1;            // 0..127
    const int acol = (tid & 1) * 4;       // 0 or 4
    // B loading: 8 rows x 128 cols = 1024 floats = 256 float4
    const int brow = tid >> 5;            // 0..7
    const int bcol = (tid & 31) * 4;      // 0..124

    const float* Aptr = A + (size_t)(by * BM + arow) * K + acol;
    const float* Bptr = B + (size_t)brow * N + bx * BN + bcol;

    const int tx = tid & 15;   // 0..15 -> col group
    const int ty = tid >> 4;   // 0..15 -> row group

    float acc[TM][TN];
    #pragma unroll
    for (int i = 0; i < TM; i++)
        #pragma unroll
        for (int j = 0; j < TN; j++)
            acc[i][j] = 0.0f;

    for (int k0 = 0; k0 < K; k0 += BK) {
        float4 av = *reinterpret_cast<const float4*>(Aptr + k0);
        float4 bv = *reinterpret_cast<const float4*>(Bptr + (size_t)k0 * N);

        As[acol + 0][arow] = av.x;
        As[acol + 1][arow] = av.y;
        As[acol + 2][arow] = av.z;
        As[acol + 3][arow] = av.w;
        *reinterpret_cast<float4*>(&Bs[brow][bcol]) = bv;
        __syncthreads();

        #pragma unroll
        for (int k = 0; k < BK; k++) {
            float a[TM], b[TN];
            float4 a0 = *reinterpret_cast<const float4*>(&As[k][ty * TM]);
            float4 a1 = *reinterpret_cast<const float4*>(&As[k][ty * TM + 4]);
            float4 b0 = *reinterpret_cast<const float4*>(&Bs[k][tx * TN]);
            float4 b1 = *reinterpret_cast<const float4*>(&Bs[k][tx * TN + 4]);
            a[0]=a0.x; a[1]=a0.y; a[2]=a0.z; a[3]=a0.w;
            a[4]=a1.x; a[5]=a1.y; a[6]=a1.z; a[7]=a1.w;
            b[0]=b0.x; b[1]=b0.y; b[2]=b0.z; b[3]=b0.w;
            b[4]=b1.x; b[5]=b1.y; b[6]=b1.z; b[7]=b1.w;
            #pragma unroll
            for (int i = 0; i < TM; i++)
                #pragma unroll
                for (int j = 0; j < TN; j++)
                    acc[i][j] = fmaf(a[i], b[j], acc[i][j]);
        }
        __syncthreads();
    }

    // Write back (vectorized)
    #pragma unroll
    for (int i = 0; i < TM; i++) {
        float* Crow = C + (size_t)(by * BM + ty * TM + i) * N + bx * BN + tx * TN;
        float4 v0 = make_float4(acc[i][0], acc[i][1], acc[i][2], acc[i][3]);
        float4 v1 = make_float4(acc[i][4], acc[i][5], acc[i][6], acc[i][7]);
        *reinterpret_cast<float4*>(Crow)     = v0;
        *reinterpret_cast<float4*>(Crow + 4) = v1;
    }
}

// ---------------------------------------------------------------------------
// Fused epilogue: per batch row b:
//   gates = LN(gh_row; ln1) + LN(gx_row; ln2) + bias     (over 4096)
//   f,i,o,c = split(gates, 4)
//   c1 = sig(f)*c0 + sig(i)*tanh(c)
//   h1 = sig(o)*tanh(LN(c1; ln3))                        (LN over 1024)
// One block (256 threads) per row.
// ---------------------------------------------------------------------------
__device__ __forceinline__ float sigmoidf_fast(float v) {
    return 1.0f / (1.0f + __expf(-v));
}
__device__ __forceinline__ float tanhf_fast(float v) {
    // tanh(v) = 1 - 2/(exp(2v)+1); clamp to avoid inf in expf
    float e = __expf(2.0f * fminf(fmaxf(v, -15.0f), 15.0f));
    return (e - 1.0f) / (e + 1.0f);
}

__device__ __forceinline__ float4 block_reduce4(float4 v) {
    __shared__ float4 sh[8];
    const int lane = threadIdx.x & 31;
    const int wid  = threadIdx.x >> 5;
    __syncthreads();  // protect sh reuse across calls
    #pragma unroll
    for (int o = 16; o > 0; o >>= 1) {
        v.x += __shfl_down_sync(0xffffffffu, v.x, o);
        v.y += __shfl_down_sync(0xffffffffu, v.y, o);
        v.z += __shfl_down_sync(0xffffffffu, v.z, o);
        v.w += __shfl_down_sync(0xffffffffu, v.w, o);
    }
    if (lane == 0) sh[wid] = v;
    __syncthreads();
    if (wid == 0) {
        v = (lane < 8) ? sh[lane] : make_float4(0.f, 0.f, 0.f, 0.f);
        #pragma unroll
        for (int o = 4; o > 0; o >>= 1) {
            v.x += __shfl_down_sync(0xffffffffu, v.x, o);
            v.y += __shfl_down_sync(0xffffffffu, v.y, o);
            v.z += __shfl_down_sync(0xffffffffu, v.z, o);
            v.w += __shfl_down_sync(0xffffffffu, v.w, o);
        }
        if (lane == 0) sh[0] = v;
    }
    __syncthreads();
    return sh[0];
}

__global__ __launch_bounds__(256, 4)
void epilogue_kernel(const float* __restrict__ c0,
                     const float* __restrict__ bias,
                     const float* __restrict__ ln1g, const float* __restrict__ ln1b,
                     const float* __restrict__ ln2g, const float* __restrict__ ln2b,
                     const float* __restrict__ ln3g, const float* __restrict__ ln3b,
                     float* __restrict__ h1, float* __restrict__ c1)
{
    const int b   = blockIdx.x;
    const int tid = threadIdx.x;
    const float* __restrict__ ghr = g_gh + (size_t)b * GDIM;
    const float* __restrict__ gxr = g_gx + (size_t)b * GDIM;

    const float EPS = 1e-5f;

    // --- Phase 1: LN stats for gh row and gx row (4096 each) ---
    float4 st = make_float4(0.f, 0.f, 0.f, 0.f);  // s_gh, q_gh, s_gx, q_gx
    #pragma unroll
    for (int it = 0; it < GDIM / 256; it++) {
        int i = tid + it * 256;
        float v = ghr[i];
        float w = gxr[i];
        st.x += v; st.y += v * v;
        st.z += w; st.w += w * w;
    }
    st = block_reduce4(st);
    const float inv4h = 1.0f / (float)GDIM;
    float mu1 = st.x * inv4h;
    float rs1 = rsqrtf(fmaxf(st.y * inv4h - mu1 * mu1, 0.f) + EPS);
    float mu2 = st.z * inv4h;
    float rs2 = rsqrtf(fmaxf(st.w * inv4h - mu2 * mu2, 0.f) + EPS);

    // --- Phase 2: gates + c1, accumulate LN3 stats ---
    float c1v[HDIM / 256];
    float ogv[HDIM / 256];
    float4 st3 = make_float4(0.f, 0.f, 0.f, 0.f);
    #pragma unroll
    for (int it = 0; it < HDIM / 256; it++) {
        int j = tid + it * 256;
        // column indices into the 4096-wide gates: f=j, i=j+H, o=j+2H, c=j+3H
        int jf = j, ji = j + HDIM, jo = j + 2 * HDIM, jc = j + 3 * HDIM;
        float gf = (ghr[jf] - mu1) * rs1 * ln1g[jf] + ln1b[jf]
                 + (gxr[jf] - mu2) * rs2 * ln2g[jf] + ln2b[jf] + bias[jf];
        float gi = (ghr[ji] - mu1) * rs1 * ln1g[ji] + ln1b[ji]
                 + (gxr[ji] - mu2) * rs2 * ln2g[ji] + ln2b[ji] + bias[ji];
        float go = (ghr[jo] - mu1) * rs1 * ln1g[jo] + ln1b[jo]
                 + (gxr[jo] - mu2) * rs2 * ln2g[jo] + ln2b[jo] + bias[jo];
        float gc = (ghr[jc] - mu1) * rs1 * ln1g[jc] + ln1b[jc]
                 + (gxr[jc] - mu2) * rs2 * ln2g[jc] + ln2b[jc] + bias[jc];

        float cv = sigmoidf_fast(gf) * c0[(size_t)b * HDIM + j]
                 + sigmoidf_fast(gi) * tanhf_fast(gc);
        c1v[it] = cv;
        ogv[it] = go;
        st3.x += cv;
        st3.y += cv * cv;
        c1[(size_t)b * HDIM + j] = cv;
    }
    st3 = block_reduce4(st3);
    const float invh = 1.0f / (float)HDIM;
    float mu3 = st3.x * invh;
    float rs3 = rsqrtf(fmaxf(st3.y * invh - mu3 * mu3, 0.f) + EPS);

    // --- Phase 3: h1 ---
    #pragma unroll
    for (int it = 0; it < HDIM / 256; it++) {
        int j = tid + it * 256;
        float lnc = (c1v[it] - mu3) * rs3 * ln3g[j] + ln3b[j];
        h1[(size_t)b * HDIM + j] = sigmoidf_fast(ogv[it]) * tanhf_fast(lnc);
    }
}

// ---------------------------------------------------------------------------
// Inputs (metadata order): x, h0, c0, weight_h, weight_x, bias,
//                          ln1_g, ln1_b, ln2_g, ln2_b, ln3_g, ln3_b
// Output: (h1, c1) concatenated -> h1 [8192*1024] then c1 [8192*1024]
// ---------------------------------------------------------------------------
extern "C" void kernel_launch(void* const* d_in, const int* in_sizes, int n_in,
                              void* d_out, int out_size)
{
    const float* x    = (const float*)d_in[0];
    const float* h0   = (const float*)d_in[1];
    const float* c0   = (const float*)d_in[2];
    const float* Wh   = (const float*)d_in[3];
    const float* Wx   = (const float*)d_in[4];
    const float* bias = (const float*)d_in[5];
    const float* ln1g = (const float*)d_in[6];
    const float* ln1b = (const float*)d_in[7];
    const float* ln2g = (const float*)d_in[8];
    const float* ln2b = (const float*)d_in[9];
    const float* ln3g = (const float*)d_in[10];
    const float* ln3b = (const float*)d_in[11];

    float* out = (float*)d_out;
    float* h1 = out;                                // first half
    float* c1 = out + (size_t)BATCH * HDIM;         // second half

    dim3 grid(GDIM / BN, BATCH / BM);
    gemm_kernel<<<grid, 256>>>(h0, Wh, BATCH, GDIM, HDIM, /*which=*/0);  // g_gh
    gemm_kernel<<<grid, 256>>>(x,  Wx, BATCH, GDIM, HDIM, /*which=*/1);  // g_gx

    epilogue_kernel<<<BATCH, 256>>>(c0, bias, ln1g, ln1b, ln2g, ln2b,
                                    ln3g, ln3b, h1, c1);
}

// round 3
// speedup vs baseline: 2.3325x; 2.3325x over previous
#include <cuda_runtime.h>
#include <cuda_bf16.h>
#include <math.h>
#include <stdint.h>

// Problem dims (fixed): B=8192, K(=D=H)=1024, 4H=4096
#define BATCH 8192
#define KDIM  1024
#define GDIM  4096

// ---------------------------------------------------------------------------
// Device-global scratch (allocation-free rule)
// ---------------------------------------------------------------------------
__device__ float g_gh[(size_t)BATCH * GDIM];   // h0 @ Wh (fp32)
__device__ float g_gx[(size_t)BATCH * GDIM];   // x  @ Wx (fp32)

// Split-precision bf16 operands. A-side: [M][K] row-major (K-major).
__device__ __nv_bfloat16 g_h0h[(size_t)BATCH * KDIM];
__device__ __nv_bfloat16 g_h0l[(size_t)BATCH * KDIM];
__device__ __nv_bfloat16 g_xh [(size_t)BATCH * KDIM];
__device__ __nv_bfloat16 g_xl [(size_t)BATCH * KDIM];
// B-side: transposed weights [N=4096][K=1024] (K-major rows)
__device__ __nv_bfloat16 g_whh[(size_t)GDIM * KDIM];
__device__ __nv_bfloat16 g_whl[(size_t)GDIM * KDIM];
__device__ __nv_bfloat16 g_wxh[(size_t)GDIM * KDIM];
__device__ __nv_bfloat16 g_wxl[(size_t)GDIM * KDIM];

// ---------------------------------------------------------------------------
// Conversion kernels (select device-global destinations via `which`)
// ---------------------------------------------------------------------------
__global__ __launch_bounds__(256)
void convert_act(const float* __restrict__ src, int which)
{
    __nv_bfloat16* hi = which ? g_xh : g_h0h;
    __nv_bfloat16* lo = which ? g_xl : g_h0l;
    size_t i = ((size_t)blockIdx.x * 256 + threadIdx.x) * 4;
    float4 v = *reinterpret_cast<const float4*>(src + i);
    float vv[4] = {v.x, v.y, v.z, v.w};
    #pragma unroll
    for (int j = 0; j < 4; j++) {
        __nv_bfloat16 h = __float2bfloat16_rn(vv[j]);
        hi[i + j] = h;
        lo[i + j] = __float2bfloat16_rn(vv[j] - __bfloat162float(h));
    }
}

// Transpose + split: W[K=1024][N=4096] -> Wt hi/lo [N][K]
__global__ __launch_bounds__(256)
void convert_wt(const float* __restrict__ W, int which)
{
    __nv_bfloat16* Th = which ? g_wxh : g_whh;
    __nv_bfloat16* Tl = which ? g_wxl : g_whl;
    __shared__ float tile[32][33];
    int tx = threadIdx.x;        // 0..31
    int ty = threadIdx.y;        // 0..7
    int n0 = blockIdx.x * 32;
    int k0 = blockIdx.y * 32;
    #pragma unroll
    for (int i = ty; i < 32; i += 8)
        tile[i][tx] = W[(size_t)(k0 + i) * GDIM + n0 + tx];
    __syncthreads();
    #pragma unroll
    for (int i = ty; i < 32; i += 8) {
        float v = tile[tx][i];   // = W[k0+tx][n0+i]
        __nv_bfloat16 h = __float2bfloat16_rn(v);
        size_t o = (size_t)(n0 + i) * KDIM + k0 + tx;
        Th[o] = h;
        Tl[o] = __float2bfloat16_rn(v - __bfloat162float(h));
    }
}

// ---------------------------------------------------------------------------
// mma.sync bf16 GEMM with 3-pass split accumulation:
//   C = Ah*Bh + Ah*Bl + Al*Bh    (fp32 accumulate)
// CTA tile 128x128, BK=32, 3-stage cp.async pipeline, 8 warps (warp 32x64).
// SMEM rows strided 80B (64B data + 16B pad) -> conflict-free ldmatrix.
// ---------------------------------------------------------------------------
#define BM 128
#define BN 128
#define BK 32
#define KTILES (KDIM / BK)      // 32
#define NTHREADS 256
#define NSTAGES 3

#define ROWB 80                  // bytes per smem row (32 bf16 + 8 pad)
#define T_AH 0
#define T_AL 10240
#define T_BH 20480
#define T_BL 30720
#define STAGE 40960
#define SMEM_TOTAL (NSTAGES * STAGE)   // 122880

__device__ __forceinline__ uint32_t smem_u32(const void* p) {
    return (uint32_t)__cvta_generic_to_shared(p);
}
__device__ __forceinline__ void cp16(uint32_t dst, const void* src) {
    asm volatile("cp.async.cg.shared.global [%0], [%1], 16;\n" :: "r"(dst), "l"(src));
}
__device__ __forceinline__ void ldsm4(uint32_t* r, uint32_t addr) {
    asm volatile("ldmatrix.sync.aligned.m8n8.x4.shared.b16 {%0,%1,%2,%3}, [%4];\n"
                 : "=r"(r[0]), "=r"(r[1]), "=r"(r[2]), "=r"(r[3]) : "r"(addr));
}
__device__ __forceinline__ void mma16816(float* d, const uint32_t* a, const uint32_t* b) {
    asm volatile(
        "mma.sync.aligned.m16n8k16.row.col.f32.bf16.bf16.f32 "
        "{%0,%1,%2,%3}, {%4,%5,%6,%7}, {%8,%9}, {%0,%1,%2,%3};\n"
        : "+f"(d[0]), "+f"(d[1]), "+f"(d[2]), "+f"(d[3])
        : "r"(a[0]), "r"(a[1]), "r"(a[2]), "r"(a[3]), "r"(b[0]), "r"(b[1]));
}

__device__ __forceinline__ void load_stage(uint32_t sb, int buf,
                                           const __nv_bfloat16* Ah, const __nv_bfloat16* Al,
                                           const __nv_bfloat16* Bh, const __nv_bfloat16* Bl,
                                           int mBase, int nBase, int k0, int tid)
{
    uint32_t st = sb + buf * STAGE;
    // 4 tiles x 128 rows x 4 chunks(16B) = 2048 chunks; 8 per thread
    #pragma unroll
    for (int it = 0; it < 2048 / NTHREADS; it++) {
        int i = tid + it * NTHREADS;
        int t = i >> 9;           // 0:Ah 1:Al 2:Bh 3:Bl
        int j = i & 511;
        int row = j >> 2;
        int c = j & 3;
        const __nv_bfloat16* src;
        uint32_t toff;
        if (t == 0)      { src = Ah + (size_t)(mBase + row) * KDIM + k0 + c * 8; toff = T_AH; }
        else if (t == 1) { src = Al + (size_t)(mBase + row) * KDIM + k0 + c * 8; toff = T_AL; }
        else if (t == 2) { src = Bh + (size_t)(nBase + row) * KDIM + k0 + c * 8; toff = T_BH; }
        else             { src = Bl + (size_t)(nBase + row) * KDIM + k0 + c * 8; toff = T_BL; }
        cp16(st + toff + (uint32_t)(row * ROWB + c * 16), src);
    }
}

__global__ __launch_bounds__(NTHREADS, 1)
void gemm_mma()
{
    extern __shared__ char smem[];
    const int which = blockIdx.z;
    const __nv_bfloat16 *Ah, *Al, *Bh, *Bl;
    float* C;
    if (which == 0) { Ah = g_h0h; Al = g_h0l; Bh = g_whh; Bl = g_whl; C = g_gh; }
    else            { Ah = g_xh;  Al = g_xl;  Bh = g_wxh; Bl = g_wxl; C = g_gx; }

    const int nBase = blockIdx.x * BN;
    const int mBase = blockIdx.y * BM;
    const int tid  = threadIdx.x;
    const int lane = tid & 31;
    const int wid  = tid >> 5;
    const int wm   = wid & 3;      // 4 warps along M
    const int wn   = wid >> 2;     // 2 warps along N
    uint32_t sb = smem_u32(smem);

    // ldmatrix per-lane address components
    // A (16x16 tile): lanes 0-15 -> rows 0-15 @k, lanes 16-31 -> rows 0-15 @k+8
    const uint32_t aOff = (uint32_t)((wm * 32 + (lane & 15)) * ROWB + (lane >> 4) * 16);
    // B (16n x 16k tile): m0=n0-7/k0-7, m1=n0-7/k8-15, m2=n8-15/k0-7, m3=n8-15/k8-15
    const uint32_t bRow = (uint32_t)(wn * 64 + ((lane >> 4) << 3) + (lane & 7));
    const uint32_t bOff = bRow * ROWB + ((lane >> 3) & 1) * 16;

    float acc[2][8][4];
    #pragma unroll
    for (int mi = 0; mi < 2; mi++)
        #pragma unroll
        for (int ni = 0; ni < 8; ni++)
            #pragma unroll
            for (int q = 0; q < 4; q++)
                acc[mi][ni][q] = 0.0f;

    // Prologue: stages 0 and 1
    load_stage(sb, 0, Ah, Al, Bh, Bl, mBase, nBase, 0,  tid);
    asm volatile("cp.async.commit_group;" ::: "memory");
    load_stage(sb, 1, Ah, Al, Bh, Bl, mBase, nBase, BK, tid);
    asm volatile("cp.async.commit_group;" ::: "memory");

    for (int k = 0; k < KTILES; k++) {
        asm volatile("cp.async.wait_group 1;" ::: "memory");
        __syncthreads();

        // Prefetch stage k+2 before computing (overlap)
        if (k + 2 < KTILES)
            load_stage(sb, (k + 2) % NSTAGES, Ah, Al, Bh, Bl, mBase, nBase,
                       (k + 2) * BK, tid);
        asm volatile("cp.async.commit_group;" ::: "memory");

        uint32_t st = sb + (k % NSTAGES) * STAGE;
        #pragma unroll
        for (int ks = 0; ks < 2; ks++) {
            uint32_t ah[2][4], al[2][4];
            ldsm4(ah[0], st + T_AH + aOff + ks * 32);
            ldsm4(ah[1], st + T_AH + aOff + 16 * ROWB + ks * 32);
            ldsm4(al[0], st + T_AL + aOff + ks * 32);
            ldsm4(al[1], st + T_AL + aOff + 16 * ROWB + ks * 32);

            uint32_t bh[8][2], bl[8][2];
            #pragma unroll
            for (int p = 0; p < 4; p++) {
                uint32_t r[4];
                ldsm4(r, st + T_BH + bOff + (uint32_t)(p * 16 * ROWB) + ks * 32);
                bh[2 * p][0] = r[0]; bh[2 * p][1] = r[1];
                bh[2 * p + 1][0] = r[2]; bh[2 * p + 1][1] = r[3];
                ldsm4(r, st + T_BL + bOff + (uint32_t)(p * 16 * ROWB) + ks * 32);
                bl[2 * p][0] = r[0]; bl[2 * p][1] = r[1];
                bl[2 * p + 1][0] = r[2]; bl[2 * p + 1][1] = r[3];
            }

            #pragma unroll
            for (int mi = 0; mi < 2; mi++)
                #pragma unroll
                for (int ni = 0; ni < 8; ni++) {
                    mma16816(acc[mi][ni], ah[mi], bh[ni]);
                    mma16816(acc[mi][ni], al[mi], bh[ni]);
                    mma16816(acc[mi][ni], ah[mi], bl[ni]);
                }
        }
        __syncthreads();
    }

    // Write back: frag (mi,ni): rows mBase+wm*32+mi*16+{l/4, l/4+8},
    // cols nBase+wn*64+ni*8+(l%4)*2
    #pragma unroll
    for (int mi = 0; mi < 2; mi++) {
        #pragma unroll
        for (int ni = 0; ni < 8; ni++) {
            int row = mBase + wm * 32 + mi * 16 + (lane >> 2);
            int col = nBase + wn * 64 + ni * 8 + (lane & 3) * 2;
            float2 v0 = make_float2(acc[mi][ni][0], acc[mi][ni][1]);
            float2 v1 = make_float2(acc[mi][ni][2], acc[mi][ni][3]);
            *reinterpret_cast<float2*>(C + (size_t)row * GDIM + col) = v0;
            *reinterpret_cast<float2*>(C + (size_t)(row + 8) * GDIM + col) = v1;
        }
    }
}

// ---------------------------------------------------------------------------
// Fused LSTM epilogue (unchanged from R1 — passed at rel_err 4.5e-7)
// ---------------------------------------------------------------------------
__device__ __forceinline__ float sigmoidf_fast(float v) {
    return 1.0f / (1.0f + __expf(-v));
}
__device__ __forceinline__ float tanhf_fast(float v) {
    float e = __expf(2.0f * fminf(fmaxf(v, -15.0f), 15.0f));
    return (e - 1.0f) / (e + 1.0f);
}

__device__ __forceinline__ float4 block_reduce4(float4 v) {
    __shared__ float4 sh[8];
    const int lane = threadIdx.x & 31;
    const int wid  = threadIdx.x >> 5;
    __syncthreads();
    #pragma unroll
    for (int o = 16; o > 0; o >>= 1) {
        v.x += __shfl_down_sync(0xffffffffu, v.x, o);
        v.y += __shfl_down_sync(0xffffffffu, v.y, o);
        v.z += __shfl_down_sync(0xffffffffu, v.z, o);
        v.w += __shfl_down_sync(0xffffffffu, v.w, o);
    }
    if (lane == 0) sh[wid] = v;
    __syncthreads();
    if (wid == 0) {
        v = (lane < 8) ? sh[lane] : make_float4(0.f, 0.f, 0.f, 0.f);
        #pragma unroll
        for (int o = 4; o > 0; o >>= 1) {
            v.x += __shfl_down_sync(0xffffffffu, v.x, o);
            v.y += __shfl_down_sync(0xffffffffu, v.y, o);
            v.z += __shfl_down_sync(0xffffffffu, v.z, o);
            v.w += __shfl_down_sync(0xffffffffu, v.w, o);
        }
        if (lane == 0) sh[0] = v;
    }
    __syncthreads();
    return sh[0];
}

__global__ __launch_bounds__(256, 4)
void epilogue_kernel(const float* __restrict__ c0,
                     const float* __restrict__ bias,
                     const float* __restrict__ ln1g, const float* __restrict__ ln1b,
                     const float* __restrict__ ln2g, const float* __restrict__ ln2b,
                     const float* __restrict__ ln3g, const float* __restrict__ ln3b,
                     float* __restrict__ h1, float* __restrict__ c1)
{
    const int b   = blockIdx.x;
    const int tid = threadIdx.x;
    const float* __restrict__ ghr = g_gh + (size_t)b * GDIM;
    const float* __restrict__ gxr = g_gx + (size_t)b * GDIM;

    const float EPS = 1e-5f;

    float4 st = make_float4(0.f, 0.f, 0.f, 0.f);
    #pragma unroll
    for (int it = 0; it < GDIM / 256; it++) {
        int i = tid + it * 256;
        float v = ghr[i];
        float w = gxr[i];
        st.x += v; st.y += v * v;
        st.z += w; st.w += w * w;
    }
    st = block_reduce4(st);
    const float inv4h = 1.0f / (float)GDIM;
    float mu1 = st.x * inv4h;
    float rs1 = rsqrtf(fmaxf(st.y * inv4h - mu1 * mu1, 0.f) + EPS);
    float mu2 = st.z * inv4h;
    float rs2 = rsqrtf(fmaxf(st.w * inv4h - mu2 * mu2, 0.f) + EPS);

    float c1v[4];
    float ogv[4];
    float4 st3 = make_float4(0.f, 0.f, 0.f, 0.f);
    #pragma unroll
    for (int it = 0; it < 4; it++) {
        int j = tid + it * 256;
        int jf = j, ji = j + 1024, jo = j + 2048, jc = j + 3072;
        float gf = (ghr[jf] - mu1) * rs1 * ln1g[jf] + ln1b[jf]
                 + (gxr[jf] - mu2) * rs2 * ln2g[jf] + ln2b[jf] + bias[jf];
        float gi = (ghr[ji] - mu1) * rs1 * ln1g[ji] + ln1b[ji]
                 + (gxr[ji] - mu2) * rs2 * ln2g[ji] + ln2b[ji] + bias[ji];
        float go = (ghr[jo] - mu1) * rs1 * ln1g[jo] + ln1b[jo]
                 + (gxr[jo] - mu2) * rs2 * ln2g[jo] + ln2b[jo] + bias[jo];
        float gc = (ghr[jc] - mu1) * rs1 * ln1g[jc] + ln1b[jc]
                 + (gxr[jc] - mu2) * rs2 * ln2g[jc] + ln2b[jc] + bias[jc];

        float cv = sigmoidf_fast(gf) * c0[(size_t)b * 1024 + j]
                 + sigmoidf_fast(gi) * tanhf_fast(gc);
        c1v[it] = cv;
        ogv[it] = go;
        st3.x += cv;
        st3.y += cv * cv;
        c1[(size_t)b * 1024 + j] = cv;
    }
    st3 = block_reduce4(st3);
    const float invh = 1.0f / 1024.0f;
    float mu3 = st3.x * invh;
    float rs3 = rsqrtf(fmaxf(st3.y * invh - mu3 * mu3, 0.f) + EPS);

    #pragma unroll
    for (int it = 0; it < 4; it++) {
        int j = tid + it * 256;
        float lnc = (c1v[it] - mu3) * rs3 * ln3g[j] + ln3b[j];
        h1[(size_t)b * 1024 + j] = sigmoidf_fast(ogv[it]) * tanhf_fast(lnc);
    }
}

// ---------------------------------------------------------------------------
// Launch: converts -> 2 GEMMs (one grid, z=2) -> fused epilogue
// ---------------------------------------------------------------------------
extern "C" void kernel_launch(void* const* d_in, const int* in_sizes, int n_in,
                              void* d_out, int out_size)
{
    const float* x    = (const float*)d_in[0];
    const float* h0   = (const float*)d_in[1];
    const float* c0   = (const float*)d_in[2];
    const float* Wh   = (const float*)d_in[3];
    const float* Wx   = (const float*)d_in[4];
    const float* bias = (const float*)d_in[5];
    const float* ln1g = (const float*)d_in[6];
    const float* ln1b = (const float*)d_in[7];
    const float* ln2g = (const float*)d_in[8];
    const float* ln2b = (const float*)d_in[9];
    const float* ln3g = (const float*)d_in[10];
    const float* ln3b = (const float*)d_in[11];

    float* out = (float*)d_out;
    float* h1 = out;
    float* c1 = out + (size_t)BATCH * KDIM;

    cudaFuncSetAttribute(gemm_mma, cudaFuncAttributeMaxDynamicSharedMemorySize,
                         SMEM_TOTAL);

    // Split-precision conversions
    {
        int blocks = (int)(((size_t)BATCH * KDIM / 4) / 256);
        convert_act<<<blocks, 256>>>(h0, 0);
        convert_act<<<blocks, 256>>>(x,  1);
        dim3 tb(32, 8);
        dim3 tg(GDIM / 32, KDIM / 32);
        convert_wt<<<tg, tb>>>(Wh, 0);
        convert_wt<<<tg, tb>>>(Wx, 1);
    }

    // Tensor-core GEMMs: grid (N tiles, M tiles, which)
    dim3 grid(GDIM / BN, BATCH / BM, 2);
    gemm_mma<<<grid, NTHREADS, SMEM_TOTAL>>>();

    epilogue_kernel<<<BATCH, 256>>>(c0, bias, ln1g, ln1b, ln2g, ln2b,
                                    ln3g, ln3b, h1, c1);
}

// round 4
// speedup vs baseline: 2.6724x; 1.1457x over previous
#include <cuda_runtime.h>
#include <cuda_bf16.h>
#include <math.h>
#include <stdint.h>

// Problem dims (fixed): B=8192, K(=D=H)=1024, 4H=4096
#define BATCH 8192
#define KDIM  1024
#define GDIM  4096

// ---------------------------------------------------------------------------
// Device-global scratch (allocation-free rule)
// ---------------------------------------------------------------------------
__device__ float g_gh[(size_t)BATCH * GDIM];   // h0 @ Wh (fp32)
__device__ float g_gx[(size_t)BATCH * GDIM];   // x  @ Wx (fp32)

// Split-precision bf16 operands. A-side: [M][K] row-major (K-major).
__device__ __nv_bfloat16 g_h0h[(size_t)BATCH * KDIM];
__device__ __nv_bfloat16 g_h0l[(size_t)BATCH * KDIM];
__device__ __nv_bfloat16 g_xh [(size_t)BATCH * KDIM];
__device__ __nv_bfloat16 g_xl [(size_t)BATCH * KDIM];
// B-side: transposed weights [N=4096][K=1024] (K-major rows)
__device__ __nv_bfloat16 g_whh[(size_t)GDIM * KDIM];
__device__ __nv_bfloat16 g_whl[(size_t)GDIM * KDIM];
__device__ __nv_bfloat16 g_wxh[(size_t)GDIM * KDIM];
__device__ __nv_bfloat16 g_wxl[(size_t)GDIM * KDIM];

// ---------------------------------------------------------------------------
// Conversion kernels (select device-global destinations via `which`)
// ---------------------------------------------------------------------------
__global__ __launch_bounds__(256)
void convert_act(const float* __restrict__ src, int which)
{
    __nv_bfloat16* hi = which ? g_xh : g_h0h;
    __nv_bfloat16* lo = which ? g_xl : g_h0l;
    size_t i = ((size_t)blockIdx.x * 256 + threadIdx.x) * 4;
    float4 v = *reinterpret_cast<const float4*>(src + i);
    float vv[4] = {v.x, v.y, v.z, v.w};
    #pragma unroll
    for (int j = 0; j < 4; j++) {
        __nv_bfloat16 h = __float2bfloat16_rn(vv[j]);
        hi[i + j] = h;
        lo[i + j] = __float2bfloat16_rn(vv[j] - __bfloat162float(h));
    }
}

// Transpose + split: W[K=1024][N=4096] -> Wt hi/lo [N][K]
__global__ __launch_bounds__(256)
void convert_wt(const float* __restrict__ W, int which)
{
    __nv_bfloat16* Th = which ? g_wxh : g_whh;
    __nv_bfloat16* Tl = which ? g_wxl : g_whl;
    __shared__ float tile[32][33];
    int tx = threadIdx.x;        // 0..31
    int ty = threadIdx.y;        // 0..7
    int n0 = blockIdx.x * 32;
    int k0 = blockIdx.y * 32;
    #pragma unroll
    for (int i = ty; i < 32; i += 8)
        tile[i][tx] = W[(size_t)(k0 + i) * GDIM + n0 + tx];
    __syncthreads();
    #pragma unroll
    for (int i = ty; i < 32; i += 8) {
        float v = tile[tx][i];   // = W[k0+tx][n0+i]
        __nv_bfloat16 h = __float2bfloat16_rn(v);
        size_t o = (size_t)(n0 + i) * KDIM + k0 + tx;
        Th[o] = h;
        Tl[o] = __float2bfloat16_rn(v - __bfloat162float(h));
    }
}

// ---------------------------------------------------------------------------
// mma.sync bf16 GEMM with 3-pass split accumulation:
//   C = Ah*Bh + Ah*Bl + Al*Bh    (fp32 accumulate)
// CTA tile 128x128, BK=32, 2-stage cp.async pipeline, 8 warps (warp 32x64),
// 2 CTAs/SM (occ 2). SMEM rows strided 80B -> conflict-free ldmatrix.
// ---------------------------------------------------------------------------
#define BM 128
#define BN 128
#define BK 32
#define KTILES (KDIM / BK)      // 32
#define NTHREADS 256
#define NSTAGES 2

#define ROWB 80                  // bytes per smem row (32 bf16 + 8 pad)
#define T_AH 0
#define T_AL 10240
#define T_BH 20480
#define T_BL 30720
#define STAGE 40960
#define SMEM_TOTAL (NSTAGES * STAGE)   // 81920 -> 2 CTAs/SM

__device__ __forceinline__ uint32_t smem_u32(const void* p) {
    return (uint32_t)__cvta_generic_to_shared(p);
}
__device__ __forceinline__ void cp16(uint32_t dst, const void* src) {
    asm volatile("cp.async.cg.shared.global [%0], [%1], 16;\n" :: "r"(dst), "l"(src));
}
__device__ __forceinline__ void ldsm4(uint32_t* r, uint32_t addr) {
    asm volatile("ldmatrix.sync.aligned.m8n8.x4.shared.b16 {%0,%1,%2,%3}, [%4];\n"
                 : "=r"(r[0]), "=r"(r[1]), "=r"(r[2]), "=r"(r[3]) : "r"(addr));
}
__device__ __forceinline__ void mma16816(float* d, const uint32_t* a, const uint32_t* b) {
    asm volatile(
        "mma.sync.aligned.m16n8k16.row.col.f32.bf16.bf16.f32 "
        "{%0,%1,%2,%3}, {%4,%5,%6,%7}, {%8,%9}, {%0,%1,%2,%3};\n"
        : "+f"(d[0]), "+f"(d[1]), "+f"(d[2]), "+f"(d[3])
        : "r"(a[0]), "r"(a[1]), "r"(a[2]), "r"(a[3]), "r"(b[0]), "r"(b[1]));
}

__device__ __forceinline__ void load_stage(uint32_t sb, int buf,
                                           const __nv_bfloat16* Ah, const __nv_bfloat16* Al,
                                           const __nv_bfloat16* Bh, const __nv_bfloat16* Bl,
                                           int mBase, int nBase, int k0, int tid)
{
    uint32_t st = sb + buf * STAGE;
    // 4 tiles x 128 rows x 4 chunks(16B) = 2048 chunks; 8 per thread
    #pragma unroll
    for (int it = 0; it < 2048 / NTHREADS; it++) {
        int i = tid + it * NTHREADS;
        int t = i >> 9;           // 0:Ah 1:Al 2:Bh 3:Bl
        int j = i & 511;
        int row = j >> 2;
        int c = j & 3;
        const __nv_bfloat16* src;
        uint32_t toff;
        if (t == 0)      { src = Ah + (size_t)(mBase + row) * KDIM + k0 + c * 8; toff = T_AH; }
        else if (t == 1) { src = Al + (size_t)(mBase + row) * KDIM + k0 + c * 8; toff = T_AL; }
        else if (t == 2) { src = Bh + (size_t)(nBase + row) * KDIM + k0 + c * 8; toff = T_BH; }
        else             { src = Bl + (size_t)(nBase + row) * KDIM + k0 + c * 8; toff = T_BL; }
        cp16(st + toff + (uint32_t)(row * ROWB + c * 16), src);
    }
}

__global__ __launch_bounds__(NTHREADS, 2)
void gemm_mma()
{
    extern __shared__ char smem[];
    const int which = blockIdx.z;
    const __nv_bfloat16 *Ah, *Al, *Bh, *Bl;
    float* C;
    if (which == 0) { Ah = g_h0h; Al = g_h0l; Bh = g_whh; Bl = g_whl; C = g_gh; }
    else            { Ah = g_xh;  Al = g_xl;  Bh = g_wxh; Bl = g_wxl; C = g_gx; }

    const int nBase = blockIdx.x * BN;
    const int mBase = blockIdx.y * BM;
    const int tid  = threadIdx.x;
    const int lane = tid & 31;
    const int wid  = tid >> 5;
    const int wm   = wid & 3;      // 4 warps along M
    const int wn   = wid >> 2;     // 2 warps along N
    uint32_t sb = smem_u32(smem);

    // ldmatrix per-lane address components
    const uint32_t aOff = (uint32_t)((wm * 32 + (lane & 15)) * ROWB + (lane >> 4) * 16);
    const uint32_t bRow = (uint32_t)(wn * 64 + ((lane >> 4) << 3) + (lane & 7));
    const uint32_t bOff = bRow * ROWB + ((lane >> 3) & 1) * 16;

    float acc[2][8][4];
    #pragma unroll
    for (int mi = 0; mi < 2; mi++)
        #pragma unroll
        for (int ni = 0; ni < 8; ni++)
            #pragma unroll
            for (int q = 0; q < 4; q++)
                acc[mi][ni][q] = 0.0f;

    // Prologue: stage 0
    load_stage(sb, 0, Ah, Al, Bh, Bl, mBase, nBase, 0, tid);
    asm volatile("cp.async.commit_group;" ::: "memory");

    for (int k = 0; k < KTILES; k++) {
        // Issue loads for next stage (buffer consumed 2 iterations ago; its
        // compute finished before the trailing __syncthreads of iter k-1).
        if (k + 1 < KTILES) {
            load_stage(sb, (k + 1) & 1, Ah, Al, Bh, Bl, mBase, nBase,
                       (k + 1) * BK, tid);
            asm volatile("cp.async.commit_group;" ::: "memory");
            asm volatile("cp.async.wait_group 1;" ::: "memory");
        } else {
            asm volatile("cp.async.wait_group 0;" ::: "memory");
        }
        __syncthreads();

        uint32_t st = sb + (k & 1) * STAGE;
        #pragma unroll
        for (int ks = 0; ks < 2; ks++) {
            uint32_t ah[2][4], al[2][4];
            ldsm4(ah[0], st + T_AH + aOff + ks * 32);
            ldsm4(ah[1], st + T_AH + aOff + 16 * ROWB + ks * 32);
            ldsm4(al[0], st + T_AL + aOff + ks * 32);
            ldsm4(al[1], st + T_AL + aOff + 16 * ROWB + ks * 32);

            // Process B in two halves (ni 0..3, 4..7) to keep regs <= 128
            #pragma unroll
            for (int h = 0; h < 2; h++) {
                uint32_t bh[4][2], bl[4][2];
                #pragma unroll
                for (int p = 0; p < 2; p++) {
                    int pp = h * 2 + p;
                    uint32_t r[4];
                    ldsm4(r, st + T_BH + bOff + (uint32_t)(pp * 16 * ROWB) + ks * 32);
                    bh[2 * p][0] = r[0]; bh[2 * p][1] = r[1];
                    bh[2 * p + 1][0] = r[2]; bh[2 * p + 1][1] = r[3];
                    ldsm4(r, st + T_BL + bOff + (uint32_t)(pp * 16 * ROWB) + ks * 32);
                    bl[2 * p][0] = r[0]; bl[2 * p][1] = r[1];
                    bl[2 * p + 1][0] = r[2]; bl[2 * p + 1][1] = r[3];
                }
                #pragma unroll
                for (int mi = 0; mi < 2; mi++)
                    #pragma unroll
                    for (int nj = 0; nj < 4; nj++) {
                        int ni = h * 4 + nj;
                        mma16816(acc[mi][ni], ah[mi], bh[nj]);
                        mma16816(acc[mi][ni], al[mi], bh[nj]);
                        mma16816(acc[mi][ni], ah[mi], bl[nj]);
                    }
            }
        }
        __syncthreads();
    }

    // Write back: frag (mi,ni): rows mBase+wm*32+mi*16+{l/4, l/4+8},
    // cols nBase+wn*64+ni*8+(l%4)*2
    #pragma unroll
    for (int mi = 0; mi < 2; mi++) {
        #pragma unroll
        for (int ni = 0; ni < 8; ni++) {
            int row = mBase + wm * 32 + mi * 16 + (lane >> 2);
            int col = nBase + wn * 64 + ni * 8 + (lane & 3) * 2;
            float2 v0 = make_float2(acc[mi][ni][0], acc[mi][ni][1]);
            float2 v1 = make_float2(acc[mi][ni][2], acc[mi][ni][3]);
            *reinterpret_cast<float2*>(C + (size_t)row * GDIM + col) = v0;
            *reinterpret_cast<float2*>(C + (size_t)(row + 8) * GDIM + col) = v1;
        }
    }
}

// ---------------------------------------------------------------------------
// Fused LSTM epilogue (unchanged — passed at rel_err 4.3e-6)
// ---------------------------------------------------------------------------
__device__ __forceinline__ float sigmoidf_fast(float v) {
    return 1.0f / (1.0f + __expf(-v));
}
__device__ __forceinline__ float tanhf_fast(float v) {
    float e = __expf(2.0f * fminf(fmaxf(v, -15.0f), 15.0f));
    return (e - 1.0f) / (e + 1.0f);
}

__device__ __forceinline__ float4 block_reduce4(float4 v) {
    __shared__ float4 sh[8];
    const int lane = threadIdx.x & 31;
    const int wid  = threadIdx.x >> 5;
    __syncthreads();
    #pragma unroll
    for (int o = 16; o > 0; o >>= 1) {
        v.x += __shfl_down_sync(0xffffffffu, v.x, o);
        v.y += __shfl_down_sync(0xffffffffu, v.y, o);
        v.z += __shfl_down_sync(0xffffffffu, v.z, o);
        v.w += __shfl_down_sync(0xffffffffu, v.w, o);
    }
    if (lane == 0) sh[wid] = v;
    __syncthreads();
    if (wid == 0) {
        v = (lane < 8) ? sh[lane] : make_float4(0.f, 0.f, 0.f, 0.f);
        #pragma unroll
        for (int o = 4; o > 0; o >>= 1) {
            v.x += __shfl_down_sync(0xffffffffu, v.x, o);
            v.y += __shfl_down_sync(0xffffffffu, v.y, o);
            v.z += __shfl_down_sync(0xffffffffu, v.z, o);
            v.w += __shfl_down_sync(0xffffffffu, v.w, o);
        }
        if (lane == 0) sh[0] = v;
    }
    __syncthreads();
    return sh[0];
}

__global__ __launch_bounds__(256, 4)
void epilogue_kernel(const float* __restrict__ c0,
                     const float* __restrict__ bias,
                     const float* __restrict__ ln1g, const float* __restrict__ ln1b,
                     const float* __restrict__ ln2g, const float* __restrict__ ln2b,
                     const float* __restrict__ ln3g, const float* __restrict__ ln3b,
                     float* __restrict__ h1, float* __restrict__ c1)
{
    const int b   = blockIdx.x;
    const int tid = threadIdx.x;
    const float* __restrict__ ghr = g_gh + (size_t)b * GDIM;
    const float* __restrict__ gxr = g_gx + (size_t)b * GDIM;

    const float EPS = 1e-5f;

    float4 st = make_float4(0.f, 0.f, 0.f, 0.f);
    #pragma unroll
    for (int it = 0; it < GDIM / 256; it++) {
        int i = tid + it * 256;
        float v = ghr[i];
        float w = gxr[i];
        st.x += v; st.y += v * v;
        st.z += w; st.w += w * w;
    }
    st = block_reduce4(st);
    const float inv4h = 1.0f / (float)GDIM;
    float mu1 = st.x * inv4h;
    float rs1 = rsqrtf(fmaxf(st.y * inv4h - mu1 * mu1, 0.f) + EPS);
    float mu2 = st.z * inv4h;
    float rs2 = rsqrtf(fmaxf(st.w * inv4h - mu2 * mu2, 0.f) + EPS);

    float c1v[4];
    float ogv[4];
    float4 st3 = make_float4(0.f, 0.f, 0.f, 0.f);
    #pragma unroll
    for (int it = 0; it < 4; it++) {
        int j = tid + it * 256;
        int jf = j, ji = j + 1024, jo = j + 2048, jc = j + 3072;
        float gf = (ghr[jf] - mu1) * rs1 * ln1g[jf] + ln1b[jf]
                 + (gxr[jf] - mu2) * rs2 * ln2g[jf] + ln2b[jf] + bias[jf];
        float gi = (ghr[ji] - mu1) * rs1 * ln1g[ji] + ln1b[ji]
                 + (gxr[ji] - mu2) * rs2 * ln2g[ji] + ln2b[ji] + bias[ji];
        float go = (ghr[jo] - mu1) * rs1 * ln1g[jo] + ln1b[jo]
                 + (gxr[jo] - mu2) * rs2 * ln2g[jo] + ln2b[jo] + bias[jo];
        float gc = (ghr[jc] - mu1) * rs1 * ln1g[jc] + ln1b[jc]
                 + (gxr[jc] - mu2) * rs2 * ln2g[jc] + ln2b[jc] + bias[jc];

        float cv = sigmoidf_fast(gf) * c0[(size_t)b * 1024 + j]
                 + sigmoidf_fast(gi) * tanhf_fast(gc);
        c1v[it] = cv;
        ogv[it] = go;
        st3.x += cv;
        st3.y += cv * cv;
        c1[(size_t)b * 1024 + j] = cv;
    }
    st3 = block_reduce4(st3);
    const float invh = 1.0f / 1024.0f;
    float mu3 = st3.x * invh;
    float rs3 = rsqrtf(fmaxf(st3.y * invh - mu3 * mu3, 0.f) + EPS);

    #pragma unroll
    for (int it = 0; it < 4; it++) {
        int j = tid + it * 256;
        float lnc = (c1v[it] - mu3) * rs3 * ln3g[j] + ln3b[j];
        h1[(size_t)b * 1024 + j] = sigmoidf_fast(ogv[it]) * tanhf_fast(lnc);
    }
}

// ---------------------------------------------------------------------------
// Launch: converts -> 2 GEMMs (one grid, z=2) -> fused epilogue
// ---------------------------------------------------------------------------
extern "C" void kernel_launch(void* const* d_in, const int* in_sizes, int n_in,
                              void* d_out, int out_size)
{
    const float* x    = (const float*)d_in[0];
    const float* h0   = (const float*)d_in[1];
    const float* c0   = (const float*)d_in[2];
    const float* Wh   = (const float*)d_in[3];
    const float* Wx   = (const float*)d_in[4];
    const float* bias = (const float*)d_in[5];
    const float* ln1g = (const float*)d_in[6];
    const float* ln1b = (const float*)d_in[7];
    const float* ln2g = (const float*)d_in[8];
    const float* ln2b = (const float*)d_in[9];
    const float* ln3g = (const float*)d_in[10];
    const float* ln3b = (const float*)d_in[11];

    float* out = (float*)d_out;
    float* h1 = out;
    float* c1 = out + (size_t)BATCH * KDIM;

    cudaFuncSetAttribute(gemm_mma, cudaFuncAttributeMaxDynamicSharedMemorySize,
                         SMEM_TOTAL);

    // Split-precision conversions
    {
        int blocks = (int)(((size_t)BATCH * KDIM / 4) / 256);
        convert_act<<<blocks, 256>>>(h0, 0);
        convert_act<<<blocks, 256>>>(x,  1);
        dim3 tb(32, 8);
        dim3 tg(GDIM / 32, KDIM / 32);
        convert_wt<<<tg, tb>>>(Wh, 0);
        convert_wt<<<tg, tb>>>(Wx, 1);
    }

    // Tensor-core GEMMs: grid (N tiles, M tiles, which)
    dim3 grid(GDIM / BN, BATCH / BM, 2);
    gemm_mma<<<grid, NTHREADS, SMEM_TOTAL>>>();

    epilogue_kernel<<<BATCH, 256>>>(c0, bias, ln1g, ln1b, ln2g, ln2b,
                                    ln3g, ln3b, h1, c1);
}

// round 5
// speedup vs baseline: 5.4676x; 2.0460x over previous
#include <cuda_runtime.h>
#include <cuda_fp16.h>
#include <math.h>
#include <stdint.h>

// Problem dims (fixed): B=8192, K(=D=H)=1024, 4H=4096
#define BATCH 8192
#define KDIM  1024
#define GDIM  4096

// ---------------------------------------------------------------------------
// Device-global scratch (allocation-free rule)
// ---------------------------------------------------------------------------
__device__ float g_gh[(size_t)BATCH * GDIM];   // h0 @ Wh (fp32)
__device__ float g_gx[(size_t)BATCH * GDIM];   // x  @ Wx (fp32)

// fp16 operands. A-side: [M][K] row-major (K-major).
__device__ __half g_h0f[(size_t)BATCH * KDIM];
__device__ __half g_xf [(size_t)BATCH * KDIM];
// B-side: transposed weights [N=4096][K=1024] (K-major rows)
__device__ __half g_whf[(size_t)GDIM * KDIM];
__device__ __half g_wxf[(size_t)GDIM * KDIM];

// ---------------------------------------------------------------------------
// Conversion kernels (select device-global destinations via `which`)
// ---------------------------------------------------------------------------
__global__ __launch_bounds__(256)
void convert_act(const float* __restrict__ src, int which)
{
    __half* dst = which ? g_xf : g_h0f;
    size_t i = ((size_t)blockIdx.x * 256 + threadIdx.x) * 4;
    float4 v = *reinterpret_cast<const float4*>(src + i);
    __half2 h0 = __floats2half2_rn(v.x, v.y);
    __half2 h1 = __floats2half2_rn(v.z, v.w);
    *reinterpret_cast<__half2*>(dst + i)     = h0;
    *reinterpret_cast<__half2*>(dst + i + 2) = h1;
}

// Transpose: W[K=1024][N=4096] -> Wt [N][K] fp16
__global__ __launch_bounds__(256)
void convert_wt(const float* __restrict__ W, int which)
{
    __half* T = which ? g_wxf : g_whf;
    __shared__ float tile[32][33];
    int tx = threadIdx.x;        // 0..31
    int ty = threadIdx.y;        // 0..7
    int n0 = blockIdx.x * 32;
    int k0 = blockIdx.y * 32;
    #pragma unroll
    for (int i = ty; i < 32; i += 8)
        tile[i][tx] = W[(size_t)(k0 + i) * GDIM + n0 + tx];
    __syncthreads();
    #pragma unroll
    for (int i = ty; i < 32; i += 8)
        T[(size_t)(n0 + i) * KDIM + k0 + tx] = __float2half_rn(tile[tx][i]);
}

// ---------------------------------------------------------------------------
// mma.sync fp16 single-pass GEMM (fp32 accumulate):  C = A * B^T
// CTA tile 128x128, BK=32, 4-stage cp.async pipeline, 8 warps (warp 32x64),
// 2 CTAs/SM. SMEM rows strided 80B -> conflict-free ldmatrix.
// ---------------------------------------------------------------------------
#define BM 128
#define BN 128
#define BK 32
#define KTILES (KDIM / BK)      // 32
#define NTHREADS 256
#define NSTAGES 4

#define ROWB 80                  // bytes per smem row (32 fp16 + 8 pad)
#define T_A 0
#define T_B 10240
#define STAGE 20480
#define SMEM_TOTAL (NSTAGES * STAGE)   // 81920 -> 2 CTAs/SM

__device__ __forceinline__ uint32_t smem_u32(const void* p) {
    return (uint32_t)__cvta_generic_to_shared(p);
}
__device__ __forceinline__ void cp16(uint32_t dst, const void* src) {
    asm volatile("cp.async.cg.shared.global [%0], [%1], 16;\n" :: "r"(dst), "l"(src));
}
__device__ __forceinline__ void ldsm4(uint32_t* r, uint32_t addr) {
    asm volatile("ldmatrix.sync.aligned.m8n8.x4.shared.b16 {%0,%1,%2,%3}, [%4];\n"
                 : "=r"(r[0]), "=r"(r[1]), "=r"(r[2]), "=r"(r[3]) : "r"(addr));
}
__device__ __forceinline__ void mma16816(float* d, const uint32_t* a, const uint32_t* b) {
    asm volatile(
        "mma.sync.aligned.m16n8k16.row.col.f32.f16.f16.f32 "
        "{%0,%1,%2,%3}, {%4,%5,%6,%7}, {%8,%9}, {%0,%1,%2,%3};\n"
        : "+f"(d[0]), "+f"(d[1]), "+f"(d[2]), "+f"(d[3])
        : "r"(a[0]), "r"(a[1]), "r"(a[2]), "r"(a[3]), "r"(b[0]), "r"(b[1]));
}

__device__ __forceinline__ void load_stage(uint32_t sb, int buf,
                                           const __half* A, const __half* B,
                                           int mBase, int nBase, int k0, int tid)
{
    uint32_t st = sb + buf * STAGE;
    // 2 tiles x 128 rows x 4 chunks(16B) = 1024 chunks; 4 per thread
    #pragma unroll
    for (int it = 0; it < 1024 / NTHREADS; it++) {
        int i = tid + it * NTHREADS;
        int t = i >> 9;           // 0:A 1:B
        int j = i & 511;
        int row = j >> 2;
        int c = j & 3;
        const __half* src;
        uint32_t toff;
        if (t == 0) { src = A + (size_t)(mBase + row) * KDIM + k0 + c * 8; toff = T_A; }
        else        { src = B + (size_t)(nBase + row) * KDIM + k0 + c * 8; toff = T_B; }
        cp16(st + toff + (uint32_t)(row * ROWB + c * 16), src);
    }
}

__global__ __launch_bounds__(NTHREADS, 2)
void gemm_mma()
{
    extern __shared__ char smem[];
    const int which = blockIdx.z;
    const __half *A, *B;
    float* C;
    if (which == 0) { A = g_h0f; B = g_whf; C = g_gh; }
    else            { A = g_xf;  B = g_wxf; C = g_gx; }

    const int nBase = blockIdx.x * BN;
    const int mBase = blockIdx.y * BM;
    const int tid  = threadIdx.x;
    const int lane = tid & 31;
    const int wid  = tid >> 5;
    const int wm   = wid & 3;      // 4 warps along M
    const int wn   = wid >> 2;     // 2 warps along N
    uint32_t sb = smem_u32(smem);

    // ldmatrix per-lane address components
    const uint32_t aOff = (uint32_t)((wm * 32 + (lane & 15)) * ROWB + (lane >> 4) * 16);
    const uint32_t bRow = (uint32_t)(wn * 64 + ((lane >> 4) << 3) + (lane & 7));
    const uint32_t bOff = bRow * ROWB + ((lane >> 3) & 1) * 16;

    float acc[2][8][4];
    #pragma unroll
    for (int mi = 0; mi < 2; mi++)
        #pragma unroll
        for (int ni = 0; ni < 8; ni++)
            #pragma unroll
            for (int q = 0; q < 4; q++)
                acc[mi][ni][q] = 0.0f;

    // Prologue: stages 0,1,2
    load_stage(sb, 0, A, B, mBase, nBase, 0,      tid);
    asm volatile("cp.async.commit_group;" ::: "memory");
    load_stage(sb, 1, A, B, mBase, nBase, BK,     tid);
    asm volatile("cp.async.commit_group;" ::: "memory");
    load_stage(sb, 2, A, B, mBase, nBase, 2 * BK, tid);
    asm volatile("cp.async.commit_group;" ::: "memory");

    for (int k = 0; k < KTILES; k++) {
        // Issue loads for stage k+3 into buffer (k+3)%4 == (k-1)%4 (consumed
        // in iteration k-1, whose compute finished at its trailing barrier).
        if (k + 3 < KTILES) {
            load_stage(sb, (k + 3) & 3, A, B, mBase, nBase, (k + 3) * BK, tid);
            asm volatile("cp.async.commit_group;" ::: "memory");
            asm volatile("cp.async.wait_group 3;" ::: "memory");
        } else {
            asm volatile("cp.async.wait_group 0;" ::: "memory");
        }
        __syncthreads();

        uint32_t st = sb + (k & 3) * STAGE;
        #pragma unroll
        for (int ks = 0; ks < 2; ks++) {
            uint32_t ah[2][4];
            ldsm4(ah[0], st + T_A + aOff + ks * 32);
            ldsm4(ah[1], st + T_A + aOff + 16 * ROWB + ks * 32);

            uint32_t bb[8][2];
            #pragma unroll
            for (int p = 0; p < 4; p++) {
                uint32_t r[4];
                ldsm4(r, st + T_B + bOff + (uint32_t)(p * 16 * ROWB) + ks * 32);
                bb[2 * p][0] = r[0]; bb[2 * p][1] = r[1];
                bb[2 * p + 1][0] = r[2]; bb[2 * p + 1][1] = r[3];
            }

            #pragma unroll
            for (int mi = 0; mi < 2; mi++)
                #pragma unroll
                for (int ni = 0; ni < 8; ni++)
                    mma16816(acc[mi][ni], ah[mi], bb[ni]);
        }
        __syncthreads();
    }

    // Write back: frag (mi,ni): rows mBase+wm*32+mi*16+{l/4, l/4+8},
    // cols nBase+wn*64+ni*8+(l%4)*2
    #pragma unroll
    for (int mi = 0; mi < 2; mi++) {
        #pragma unroll
        for (int ni = 0; ni < 8; ni++) {
            int row = mBase + wm * 32 + mi * 16 + (lane >> 2);
            int col = nBase + wn * 64 + ni * 8 + (lane & 3) * 2;
            float2 v0 = make_float2(acc[mi][ni][0], acc[mi][ni][1]);
            float2 v1 = make_float2(acc[mi][ni][2], acc[mi][ni][3]);
            *reinterpret_cast<float2*>(C + (size_t)row * GDIM + col) = v0;
            *reinterpret_cast<float2*>(C + (size_t)(row + 8) * GDIM + col) = v1;
        }
    }
}

// ---------------------------------------------------------------------------
// Fused LSTM epilogue (unchanged — validated)
// ---------------------------------------------------------------------------
__device__ __forceinline__ float sigmoidf_fast(float v) {
    return 1.0f / (1.0f + __expf(-v));
}
__device__ __forceinline__ float tanhf_fast(float v) {
    float e = __expf(2.0f * fminf(fmaxf(v, -15.0f), 15.0f));
    return (e - 1.0f) / (e + 1.0f);
}

__device__ __forceinline__ float4 block_reduce4(float4 v) {
    __shared__ float4 sh[8];
    const int lane = threadIdx.x & 31;
    const int wid  = threadIdx.x >> 5;
    __syncthreads();
    #pragma unroll
    for (int o = 16; o > 0; o >>= 1) {
        v.x += __shfl_down_sync(0xffffffffu, v.x, o);
        v.y += __shfl_down_sync(0xffffffffu, v.y, o);
        v.z += __shfl_down_sync(0xffffffffu, v.z, o);
        v.w += __shfl_down_sync(0xffffffffu, v.w, o);
    }
    if (lane == 0) sh[wid] = v;
    __syncthreads();
    if (wid == 0) {
        v = (lane < 8) ? sh[lane] : make_float4(0.f, 0.f, 0.f, 0.f);
        #pragma unroll
        for (int o = 4; o > 0; o >>= 1) {
            v.x += __shfl_down_sync(0xffffffffu, v.x, o);
            v.y += __shfl_down_sync(0xffffffffu, v.y, o);
            v.z += __shfl_down_sync(0xffffffffu, v.z, o);
            v.w += __shfl_down_sync(0xffffffffu, v.w, o);
        }
        if (lane == 0) sh[0] = v;
    }
    __syncthreads();
    return sh[0];
}

__global__ __launch_bounds__(256, 4)
void epilogue_kernel(const float* __restrict__ c0,
                     const float* __restrict__ bias,
                     const float* __restrict__ ln1g, const float* __restrict__ ln1b,
                     const float* __restrict__ ln2g, const float* __restrict__ ln2b,
                     const float* __restrict__ ln3g, const float* __restrict__ ln3b,
                     float* __restrict__ h1, float* __restrict__ c1)
{
    const int b   = blockIdx.x;
    const int tid = threadIdx.x;
    const float* __restrict__ ghr = g_gh + (size_t)b * GDIM;
    const float* __restrict__ gxr = g_gx + (size_t)b * GDIM;

    const float EPS = 1e-5f;

    float4 st = make_float4(0.f, 0.f, 0.f, 0.f);
    #pragma unroll
    for (int it = 0; it < GDIM / 256; it++) {
        int i = tid + it * 256;
        float v = ghr[i];
        float w = gxr[i];
        st.x += v; st.y += v * v;
        st.z += w; st.w += w * w;
    }
    st = block_reduce4(st);
    const float inv4h = 1.0f / (float)GDIM;
    float mu1 = st.x * inv4h;
    float rs1 = rsqrtf(fmaxf(st.y * inv4h - mu1 * mu1, 0.f) + EPS);
    float mu2 = st.z * inv4h;
    float rs2 = rsqrtf(fmaxf(st.w * inv4h - mu2 * mu2, 0.f) + EPS);

    float c1v[4];
    float ogv[4];
    float4 st3 = make_float4(0.f, 0.f, 0.f, 0.f);
    #pragma unroll
    for (int it = 0; it < 4; it++) {
        int j = tid + it * 256;
        int jf = j, ji = j + 1024, jo = j + 2048, jc = j + 3072;
        float gf = (ghr[jf] - mu1) * rs1 * ln1g[jf] + ln1b[jf]
                 + (gxr[jf] - mu2) * rs2 * ln2g[jf] + ln2b[jf] + bias[jf];
        float gi = (ghr[ji] - mu1) * rs1 * ln1g[ji] + ln1b[ji]
                 + (gxr[ji] - mu2) * rs2 * ln2g[ji] + ln2b[ji] + bias[ji];
        float go = (ghr[jo] - mu1) * rs1 * ln1g[jo] + ln1b[jo]
                 + (gxr[jo] - mu2) * rs2 * ln2g[jo] + ln2b[jo] + bias[jo];
        float gc = (ghr[jc] - mu1) * rs1 * ln1g[jc] + ln1b[jc]
                 + (gxr[jc] - mu2) * rs2 * ln2g[jc] + ln2b[jc] + bias[jc];

        float cv = sigmoidf_fast(gf) * c0[(size_t)b * 1024 + j]
                 + sigmoidf_fast(gi) * tanhf_fast(gc);
        c1v[it] = cv;
        ogv[it] = go;
        st3.x += cv;
        st3.y += cv * cv;
        c1[(size_t)b * 1024 + j] = cv;
    }
    st3 = block_reduce4(st3);
    const float invh = 1.0f / 1024.0f;
    float mu3 = st3.x * invh;
    float rs3 = rsqrtf(fmaxf(st3.y * invh - mu3 * mu3, 0.f) + EPS);

    #pragma unroll
    for (int it = 0; it < 4; it++) {
        int j = tid + it * 256;
        float lnc = (c1v[it] - mu3) * rs3 * ln3g[j] + ln3b[j];
        h1[(size_t)b * 1024 + j] = sigmoidf_fast(ogv[it]) * tanhf_fast(lnc);
    }
}

// ---------------------------------------------------------------------------
// Launch: converts -> 2 GEMMs (one grid, z=2) -> fused epilogue
// ---------------------------------------------------------------------------
extern "C" void kernel_launch(void* const* d_in, const int* in_sizes, int n_in,
                              void* d_out, int out_size)
{
    const float* x    = (const float*)d_in[0];
    const float* h0   = (const float*)d_in[1];
    const float* c0   = (const float*)d_in[2];
    const float* Wh   = (const float*)d_in[3];
    const float* Wx   = (const float*)d_in[4];
    const float* bias = (const float*)d_in[5];
    const float* ln1g = (const float*)d_in[6];
    const float* ln1b = (const float*)d_in[7];
    const float* ln2g = (const float*)d_in[8];
    const float* ln2b = (const float*)d_in[9];
    const float* ln3g = (const float*)d_in[10];
    const float* ln3b = (const float*)d_in[11];

    float* out = (float*)d_out;
    float* h1 = out;
    float* c1 = out + (size_t)BATCH * KDIM;

    cudaFuncSetAttribute(gemm_mma, cudaFuncAttributeMaxDynamicSharedMemorySize,
                         SMEM_TOTAL);

    // fp16 conversions
    {
        int blocks = (int)(((size_t)BATCH * KDIM / 4) / 256);
        convert_act<<<blocks, 256>>>(h0, 0);
        convert_act<<<blocks, 256>>>(x,  1);
        dim3 tb(32, 8);
        dim3 tg(GDIM / 32, KDIM / 32);
        convert_wt<<<tg, tb>>>(Wh, 0);
        convert_wt<<<tg, tb>>>(Wx, 1);
    }

    // Tensor-core GEMMs: grid (N tiles, M tiles, which)
    dim3 grid(GDIM / BN, BATCH / BM, 2);
    gemm_mma<<<grid, NTHREADS, SMEM_TOTAL>>>();

    epilogue_kernel<<<BATCH, 256>>>(c0, bias, ln1g, ln1b, ln2g, ln2b,
                                    ln3g, ln3b, h1, c1);
}

// round 6
// speedup vs baseline: 5.4762x; 1.0016x over previous
#include <cuda_runtime.h>
#include <cuda_fp16.h>
#include <math.h>
#include <stdint.h>

// Problem dims (fixed): B=8192, K(=D=H)=1024, 4H=4096
#define BATCH 8192
#define KDIM  1024
#define GDIM  4096

// ---------------------------------------------------------------------------
// Device-global scratch (allocation-free rule)
// ---------------------------------------------------------------------------
__device__ float g_gh[(size_t)BATCH * GDIM];   // h0 @ Wh (fp32)
__device__ float g_gx[(size_t)BATCH * GDIM];   // x  @ Wx (fp32)

// fp16 operands. A-side: [M][K] row-major (K-major).
__device__ __half g_h0f[(size_t)BATCH * KDIM];
__device__ __half g_xf [(size_t)BATCH * KDIM];
// B-side: transposed weights [N=4096][K=1024] (K-major rows)
__device__ __half g_whf[(size_t)GDIM * KDIM];
__device__ __half g_wxf[(size_t)GDIM * KDIM];

// ---------------------------------------------------------------------------
// Conversion kernels
// ---------------------------------------------------------------------------
__global__ __launch_bounds__(256)
void convert_act(const float* __restrict__ src, int which)
{
    __half* dst = which ? g_xf : g_h0f;
    size_t i = ((size_t)blockIdx.x * 256 + threadIdx.x) * 4;
    float4 v = *reinterpret_cast<const float4*>(src + i);
    __half2 h0 = __floats2half2_rn(v.x, v.y);
    __half2 h1 = __floats2half2_rn(v.z, v.w);
    *reinterpret_cast<__half2*>(dst + i)     = h0;
    *reinterpret_cast<__half2*>(dst + i + 2) = h1;
}

// Transpose: W[K=1024][N=4096] -> Wt [N][K] fp16
__global__ __launch_bounds__(256)
void convert_wt(const float* __restrict__ W, int which)
{
    __half* T = which ? g_wxf : g_whf;
    __shared__ float tile[32][33];
    int tx = threadIdx.x;        // 0..31
    int ty = threadIdx.y;        // 0..7
    int n0 = blockIdx.x * 32;
    int k0 = blockIdx.y * 32;
    #pragma unroll
    for (int i = ty; i < 32; i += 8)
        tile[i][tx] = W[(size_t)(k0 + i) * GDIM + n0 + tx];
    __syncthreads();
    #pragma unroll
    for (int i = ty; i < 32; i += 8)
        T[(size_t)(n0 + i) * KDIM + k0 + tx] = __float2half_rn(tile[tx][i]);
}

// ---------------------------------------------------------------------------
// mma.sync fp16 single-pass GEMM (fp32 accumulate):  C = A * B^T
// CTA tile 128x128, BK=32, 4-stage cp.async pipeline, 8 warps (warp 32x64),
// 2 CTAs/SM. Fragment-level software pipelining across 4 (ks,half) steps.
// ---------------------------------------------------------------------------
#define BM 128
#define BN 128
#define BK 32
#define KTILES (KDIM / BK)      // 32
#define NTHREADS 256
#define NSTAGES 4

#define ROWB 80                  // bytes per smem row (32 fp16 + 8 pad)
#define T_A 0
#define T_B 10240
#define STAGE 20480
#define SMEM_TOTAL (NSTAGES * STAGE)   // 81920 -> 2 CTAs/SM

__device__ __forceinline__ uint32_t smem_u32(const void* p) {
    return (uint32_t)__cvta_generic_to_shared(p);
}
__device__ __forceinline__ void cp16(uint32_t dst, const void* src) {
    asm volatile("cp.async.cg.shared.global [%0], [%1], 16;\n" :: "r"(dst), "l"(src));
}
__device__ __forceinline__ void ldsm4(uint32_t* r, uint32_t addr) {
    asm volatile("ldmatrix.sync.aligned.m8n8.x4.shared.b16 {%0,%1,%2,%3}, [%4];\n"
                 : "=r"(r[0]), "=r"(r[1]), "=r"(r[2]), "=r"(r[3]) : "r"(addr));
}
__device__ __forceinline__ void mma16816(float* d, const uint32_t* a, const uint32_t* b) {
    asm volatile(
        "mma.sync.aligned.m16n8k16.row.col.f32.f16.f16.f32 "
        "{%0,%1,%2,%3}, {%4,%5,%6,%7}, {%8,%9}, {%0,%1,%2,%3};\n"
        : "+f"(d[0]), "+f"(d[1]), "+f"(d[2]), "+f"(d[3])
        : "r"(a[0]), "r"(a[1]), "r"(a[2]), "r"(a[3]), "r"(b[0]), "r"(b[1]));
}

__device__ __forceinline__ void load_stage(uint32_t sb, int buf,
                                           const __half* A, const __half* B,
                                           int mBase, int nBase, int k0, int tid)
{
    uint32_t st = sb + buf * STAGE;
    #pragma unroll
    for (int it = 0; it < 1024 / NTHREADS; it++) {
        int i = tid + it * NTHREADS;
        int t = i >> 9;           // 0:A 1:B
        int j = i & 511;
        int row = j >> 2;
        int c = j & 3;
        const __half* src;
        uint32_t toff;
        if (t == 0) { src = A + (size_t)(mBase + row) * KDIM + k0 + c * 8; toff = T_A; }
        else        { src = B + (size_t)(nBase + row) * KDIM + k0 + c * 8; toff = T_B; }
        cp16(st + toff + (uint32_t)(row * ROWB + c * 16), src);
    }
}

// Load one B half (4 nj tiles, one ks) into bf[p]
#define LOAD_B(p, ksv, hv) do {                                                   \
    uint32_t r[4];                                                                \
    ldsm4(r, st + T_B + bOff + (uint32_t)(((hv) * 2 + 0) * 16 * ROWB) + (ksv) * 32); \
    bf[p][0][0] = r[0]; bf[p][0][1] = r[1]; bf[p][1][0] = r[2]; bf[p][1][1] = r[3]; \
    ldsm4(r, st + T_B + bOff + (uint32_t)(((hv) * 2 + 1) * 16 * ROWB) + (ksv) * 32); \
    bf[p][2][0] = r[0]; bf[p][2][1] = r[1]; bf[p][3][0] = r[2]; bf[p][3][1] = r[3]; \
} while (0)

__global__ __launch_bounds__(NTHREADS, 2)
void gemm_mma()
{
    extern __shared__ char smem[];
    const int which = blockIdx.z;
    const __half *A, *B;
    float* C;
    if (which == 0) { A = g_h0f; B = g_whf; C = g_gh; }
    else            { A = g_xf;  B = g_wxf; C = g_gx; }

    const int nBase = blockIdx.x * BN;
    const int mBase = blockIdx.y * BM;
    const int tid  = threadIdx.x;
    const int lane = tid & 31;
    const int wid  = tid >> 5;
    const int wm   = wid & 3;      // 4 warps along M
    const int wn   = wid >> 2;     // 2 warps along N
    uint32_t sb = smem_u32(smem);

    const uint32_t aOff = (uint32_t)((wm * 32 + (lane & 15)) * ROWB + (lane >> 4) * 16);
    const uint32_t bRow = (uint32_t)(wn * 64 + ((lane >> 4) << 3) + (lane & 7));
    const uint32_t bOff = bRow * ROWB + ((lane >> 3) & 1) * 16;

    float acc[2][8][4];
    #pragma unroll
    for (int mi = 0; mi < 2; mi++)
        #pragma unroll
        for (int ni = 0; ni < 8; ni++)
            #pragma unroll
            for (int q = 0; q < 4; q++)
                acc[mi][ni][q] = 0.0f;

    // Prologue: stages 0,1,2
    load_stage(sb, 0, A, B, mBase, nBase, 0,      tid);
    asm volatile("cp.async.commit_group;" ::: "memory");
    load_stage(sb, 1, A, B, mBase, nBase, BK,     tid);
    asm volatile("cp.async.commit_group;" ::: "memory");
    load_stage(sb, 2, A, B, mBase, nBase, 2 * BK, tid);
    asm volatile("cp.async.commit_group;" ::: "memory");

    for (int k = 0; k < KTILES; k++) {
        if (k + 3 < KTILES) {
            load_stage(sb, (k + 3) & 3, A, B, mBase, nBase, (k + 3) * BK, tid);
            asm volatile("cp.async.commit_group;" ::: "memory");
            asm volatile("cp.async.wait_group 3;" ::: "memory");
        } else {
            asm volatile("cp.async.wait_group 0;" ::: "memory");
        }
        __syncthreads();

        uint32_t st = sb + (k & 3) * STAGE;

        // Fragment pipeline over 4 steps: s=(ks<<1)|h, B double-buffered.
        uint32_t af[2][2][4];     // [ks][mi][4]
        uint32_t bf[2][4][2];     // [parity][nj][2]

        ldsm4(af[0][0], st + T_A + aOff);
        ldsm4(af[0][1], st + T_A + aOff + 16 * ROWB);
        LOAD_B(0, 0, 0);
        ldsm4(af[1][0], st + T_A + aOff + 32);
        ldsm4(af[1][1], st + T_A + aOff + 16 * ROWB + 32);

        #pragma unroll
        for (int s = 0; s < 4; s++) {
            const int ks = s >> 1;
            const int h  = s & 1;
            const int cur = s & 1;
            if (s < 3) {
                const int ns = s + 1;
                LOAD_B(ns & 1, ns >> 1, ns & 1);
            }
            #pragma unroll
            for (int mi = 0; mi < 2; mi++)
                #pragma unroll
                for (int nj = 0; nj < 4; nj++)
                    mma16816(acc[mi][h * 4 + nj], af[ks][mi], bf[cur][nj]);
        }
        __syncthreads();
    }

    // Write back
    #pragma unroll
    for (int mi = 0; mi < 2; mi++) {
        #pragma unroll
        for (int ni = 0; ni < 8; ni++) {
            int row = mBase + wm * 32 + mi * 16 + (lane >> 2);
            int col = nBase + wn * 64 + ni * 8 + (lane & 3) * 2;
            float2 v0 = make_float2(acc[mi][ni][0], acc[mi][ni][1]);
            float2 v1 = make_float2(acc[mi][ni][2], acc[mi][ni][3]);
            *reinterpret_cast<float2*>(C + (size_t)row * GDIM + col) = v0;
            *reinterpret_cast<float2*>(C + (size_t)(row + 8) * GDIM + col) = v1;
        }
    }
}

// ---------------------------------------------------------------------------
// Fused LSTM epilogue with smem row caching (single global read of gates)
// ---------------------------------------------------------------------------
__device__ __forceinline__ float sigmoidf_fast(float v) {
    return 1.0f / (1.0f + __expf(-v));
}
__device__ __forceinline__ float tanhf_fast(float v) {
    float e = __expf(2.0f * fminf(fmaxf(v, -15.0f), 15.0f));
    return (e - 1.0f) / (e + 1.0f);
}

__device__ __forceinline__ float4 block_reduce4(float4 v) {
    __shared__ float4 sh[8];
    const int lane = threadIdx.x & 31;
    const int wid  = threadIdx.x >> 5;
    __syncthreads();
    #pragma unroll
    for (int o = 16; o > 0; o >>= 1) {
        v.x += __shfl_down_sync(0xffffffffu, v.x, o);
        v.y += __shfl_down_sync(0xffffffffu, v.y, o);
        v.z += __shfl_down_sync(0xffffffffu, v.z, o);
        v.w += __shfl_down_sync(0xffffffffu, v.w, o);
    }
    if (lane == 0) sh[wid] = v;
    __syncthreads();
    if (wid == 0) {
        v = (lane < 8) ? sh[lane] : make_float4(0.f, 0.f, 0.f, 0.f);
        #pragma unroll
        for (int o = 4; o > 0; o >>= 1) {
            v.x += __shfl_down_sync(0xffffffffu, v.x, o);
            v.y += __shfl_down_sync(0xffffffffu, v.y, o);
            v.z += __shfl_down_sync(0xffffffffu, v.z, o);
            v.w += __shfl_down_sync(0xffffffffu, v.w, o);
        }
        if (lane == 0) sh[0] = v;
    }
    __syncthreads();
    return sh[0];
}

__global__ __launch_bounds__(256, 4)
void epilogue_kernel(const float* __restrict__ c0,
                     const float* __restrict__ bias,
                     const float* __restrict__ ln1g, const float* __restrict__ ln1b,
                     const float* __restrict__ ln2g, const float* __restrict__ ln2b,
                     const float* __restrict__ ln3g, const float* __restrict__ ln3b,
                     float* __restrict__ h1, float* __restrict__ c1)
{
    __shared__ float sgh[GDIM];
    __shared__ float sgx[GDIM];

    const int b   = blockIdx.x;
    const int tid = threadIdx.x;
    const float4* __restrict__ ghr = reinterpret_cast<const float4*>(g_gh + (size_t)b * GDIM);
    const float4* __restrict__ gxr = reinterpret_cast<const float4*>(g_gx + (size_t)b * GDIM);

    const float EPS = 1e-5f;

    // --- Single global read: cache rows in smem, accumulate LN1/LN2 stats ---
    float4 st = make_float4(0.f, 0.f, 0.f, 0.f);
    #pragma unroll
    for (int it = 0; it < 4; it++) {
        int i = tid + it * 256;              // float4 index
        float4 v = ghr[i];
        float4 w = gxr[i];
        *reinterpret_cast<float4*>(&sgh[i * 4]) = v;
        *reinterpret_cast<float4*>(&sgx[i * 4]) = w;
        st.x += v.x + v.y + v.z + v.w;
        st.y += v.x * v.x + v.y * v.y + v.z * v.z + v.w * v.w;
        st.z += w.x + w.y + w.z + w.w;
        st.w += w.x * w.x + w.y * w.y + w.z * w.z + w.w * w.w;
    }
    st = block_reduce4(st);   // leading __syncthreads also publishes sgh/sgx
    const float inv4h = 1.0f / (float)GDIM;
    float mu1 = st.x * inv4h;
    float rs1 = rsqrtf(fmaxf(st.y * inv4h - mu1 * mu1, 0.f) + EPS);
    float mu2 = st.z * inv4h;
    float rs2 = rsqrtf(fmaxf(st.w * inv4h - mu2 * mu2, 0.f) + EPS);

    // --- Gates + c1 from smem, accumulate LN3 stats ---
    float c1v[4];
    float ogv[4];
    float4 st3 = make_float4(0.f, 0.f, 0.f, 0.f);
    #pragma unroll
    for (int it = 0; it < 4; it++) {
        int j = tid + it * 256;
        int jf = j, ji = j + 1024, jo = j + 2048, jc = j + 3072;
        float gf = (sgh[jf] - mu1) * rs1 * ln1g[jf] + ln1b[jf]
                 + (sgx[jf] - mu2) * rs2 * ln2g[jf] + ln2b[jf] + bias[jf];
        float gi = (sgh[ji] - mu1) * rs1 * ln1g[ji] + ln1b[ji]
                 + (sgx[ji] - mu2) * rs2 * ln2g[ji] + ln2b[ji] + bias[ji];
        float go = (sgh[jo] - mu1) * rs1 * ln1g[jo] + ln1b[jo]
                 + (sgx[jo] - mu2) * rs2 * ln2g[jo] + ln2b[jo] + bias[jo];
        float gc = (sgh[jc] - mu1) * rs1 * ln1g[jc] + ln1b[jc]
                 + (sgx[jc] - mu2) * rs2 * ln2g[jc] + ln2b[jc] + bias[jc];

        float cv = sigmoidf_fast(gf) * c0[(size_t)b * 1024 + j]
                 + sigmoidf_fast(gi) * tanhf_fast(gc);
        c1v[it] = cv;
        ogv[it] = go;
        st3.x += cv;
        st3.y += cv * cv;
        c1[(size_t)b * 1024 + j] = cv;
    }
    st3 = block_reduce4(st3);
    const float invh = 1.0f / 1024.0f;
    float mu3 = st3.x * invh;
    float rs3 = rsqrtf(fmaxf(st3.y * invh - mu3 * mu3, 0.f) + EPS);

    #pragma unroll
    for (int it = 0; it < 4; it++) {
        int j = tid + it * 256;
        float lnc = (c1v[it] - mu3) * rs3 * ln3g[j] + ln3b[j];
        h1[(size_t)b * 1024 + j] = sigmoidf_fast(ogv[it]) * tanhf_fast(lnc);
    }
}

// ---------------------------------------------------------------------------
// Launch: converts -> 2 GEMMs (one grid, z=2) -> fused epilogue
// ---------------------------------------------------------------------------
extern "C" void kernel_launch(void* const* d_in, const int* in_sizes, int n_in,
                              void* d_out, int out_size)
{
    const float* x    = (const float*)d_in[0];
    const float* h0   = (const float*)d_in[1];
    const float* c0   = (const float*)d_in[2];
    const float* Wh   = (const float*)d_in[3];
    const float* Wx   = (const float*)d_in[4];
    const float* bias = (const float*)d_in[5];
    const float* ln1g = (const float*)d_in[6];
    const float* ln1b = (const float*)d_in[7];
    const float* ln2g = (const float*)d_in[8];
    const float* ln2b = (const float*)d_in[9];
    const float* ln3g = (const float*)d_in[10];
    const float* ln3b = (const float*)d_in[11];

    float* out = (float*)d_out;
    float* h1 = out;
    float* c1 = out + (size_t)BATCH * KDIM;

    cudaFuncSetAttribute(gemm_mma, cudaFuncAttributeMaxDynamicSharedMemorySize,
                         SMEM_TOTAL);

    // fp16 conversions
    {
        int blocks = (int)(((size_t)BATCH * KDIM / 4) / 256);
        convert_act<<<blocks, 256>>>(h0, 0);
        convert_act<<<blocks, 256>>>(x,  1);
        dim3 tb(32, 8);
        dim3 tg(GDIM / 32, KDIM / 32);
        convert_wt<<<tg, tb>>>(Wh, 0);
        convert_wt<<<tg, tb>>>(Wx, 1);
    }

    // Tensor-core GEMMs: grid (N tiles, M tiles, which)
    dim3 grid(GDIM / BN, BATCH / BM, 2);
    gemm_mma<<<grid, NTHREADS, SMEM_TOTAL>>>();

    epilogue_kernel<<<BATCH, 256>>>(c0, bias, ln1g, ln1b, ln2g, ln2b,
                                    ln3g, ln3b, h1, c1);
}

// round 7
// speedup vs baseline: 6.4107x; 1.1706x over previous
#include <cuda_runtime.h>
#include <cuda_fp16.h>
#include <math.h>
#include <stdint.h>

// Problem dims (fixed): B=8192, K(=D=H)=1024, 4H=4096
#define BATCH 8192
#define KDIM  1024
#define GDIM  4096

// ---------------------------------------------------------------------------
// Device-global scratch (allocation-free rule)
// ---------------------------------------------------------------------------
__device__ float g_gh[(size_t)BATCH * GDIM];   // h0 @ Wh (fp32)
__device__ float g_gx[(size_t)BATCH * GDIM];   // x  @ Wx (fp32)

// fp16 operands. A-side: [M][K] row-major (K-major).
__device__ __half g_h0f[(size_t)BATCH * KDIM];
__device__ __half g_xf [(size_t)BATCH * KDIM];
// B-side: transposed weights [N=4096][K=1024] (K-major rows)
__device__ __half g_whf[(size_t)GDIM * KDIM];
__device__ __half g_wxf[(size_t)GDIM * KDIM];

// ---------------------------------------------------------------------------
// Conversion kernels
// ---------------------------------------------------------------------------
__global__ __launch_bounds__(256)
void convert_act(const float* __restrict__ src, int which)
{
    __half* dst = which ? g_xf : g_h0f;
    size_t i = ((size_t)blockIdx.x * 256 + threadIdx.x) * 4;
    float4 v = *reinterpret_cast<const float4*>(src + i);
    __half2 h0 = __floats2half2_rn(v.x, v.y);
    __half2 h1 = __floats2half2_rn(v.z, v.w);
    *reinterpret_cast<__half2*>(dst + i)     = h0;
    *reinterpret_cast<__half2*>(dst + i + 2) = h1;
}

// Transpose: W[K=1024][N=4096] -> Wt [N][K] fp16. 64x64 tiles, 256 threads.
__global__ __launch_bounds__(256)
void convert_wt(const float* __restrict__ W, int which)
{
    __half* T = which ? g_wxf : g_whf;
    __shared__ float tile[64][65];
    const int tid = threadIdx.x;
    const int n0 = blockIdx.x * 64;
    const int k0 = blockIdx.y * 64;
    // Load 64(k) x 64(n) floats via float4: 1024 float4, 4 per thread
    #pragma unroll
    for (int it = 0; it < 4; it++) {
        int i = tid + it * 256;
        int r = i >> 4;           // k row 0..63
        int c4 = i & 15;          // float4 col
        float4 v = *reinterpret_cast<const float4*>(
            &W[(size_t)(k0 + r) * GDIM + n0 + c4 * 4]);
        tile[r][c4 * 4 + 0] = v.x;
        tile[r][c4 * 4 + 1] = v.y;
        tile[r][c4 * 4 + 2] = v.z;
        tile[r][c4 * 4 + 3] = v.w;
    }
    __syncthreads();
    // Write transposed: 64(n) rows x 64(k), half2 stores (coalesced in k)
    #pragma unroll
    for (int it = 0; it < 8; it++) {
        int i = tid + it * 256;   // half2 index, 2048 total
        int n = i >> 5;           // 0..63
        int k2 = i & 31;          // half2 within row
        __half2 hv = __floats2half2_rn(tile[k2 * 2][n], tile[k2 * 2 + 1][n]);
        *reinterpret_cast<__half2*>(&T[(size_t)(n0 + n) * KDIM + k0 + k2 * 2]) = hv;
    }
}

// ---------------------------------------------------------------------------
// mma.sync fp16 single-pass GEMM (fp32 accumulate):  C = A * B^T
// CTA tile 128x128, BK=64, 2-stage cp.async pipeline, 8 warps (warp 32x64),
// 2 CTAs/SM. Fragment-level software pipelining across 8 (ks,half) steps.
// ---------------------------------------------------------------------------
#define BM 128
#define BN 128
#define BK 64
#define KTILES (KDIM / BK)      // 16
#define NTHREADS 256
#define NSTAGES 2

#define ROWB 144                 // bytes per smem row (64 fp16 + 16 pad)
#define T_A 0
#define T_B (128 * ROWB)         // 18432
#define STAGE (2 * 128 * ROWB)   // 36864
#define SMEM_TOTAL (NSTAGES * STAGE)   // 73728 -> 2 CTAs/SM

__device__ __forceinline__ uint32_t smem_u32(const void* p) {
    return (uint32_t)__cvta_generic_to_shared(p);
}
__device__ __forceinline__ void cp16(uint32_t dst, const void* src) {
    asm volatile("cp.async.cg.shared.global [%0], [%1], 16;\n" :: "r"(dst), "l"(src));
}
__device__ __forceinline__ void ldsm4(uint32_t* r, uint32_t addr) {
    asm volatile("ldmatrix.sync.aligned.m8n8.x4.shared.b16 {%0,%1,%2,%3}, [%4];\n"
                 : "=r"(r[0]), "=r"(r[1]), "=r"(r[2]), "=r"(r[3]) : "r"(addr));
}
__device__ __forceinline__ void mma16816(float* d, const uint32_t* a, const uint32_t* b) {
    asm volatile(
        "mma.sync.aligned.m16n8k16.row.col.f32.f16.f16.f32 "
        "{%0,%1,%2,%3}, {%4,%5,%6,%7}, {%8,%9}, {%0,%1,%2,%3};\n"
        : "+f"(d[0]), "+f"(d[1]), "+f"(d[2]), "+f"(d[3])
        : "r"(a[0]), "r"(a[1]), "r"(a[2]), "r"(a[3]), "r"(b[0]), "r"(b[1]));
}

__device__ __forceinline__ void load_stage(uint32_t sb, int buf,
                                           const __half* A, const __half* B,
                                           int mBase, int nBase, int k0, int tid)
{
    uint32_t st = sb + buf * STAGE;
    // 2 tiles x 128 rows x 8 chunks(16B) = 2048 chunks; 8 per thread
    #pragma unroll
    for (int it = 0; it < 2048 / NTHREADS; it++) {
        int i = tid + it * NTHREADS;
        int t = i >> 10;          // 0:A 1:B
        int j = i & 1023;
        int row = j >> 3;
        int c = j & 7;
        const __half* src;
        uint32_t toff;
        if (t == 0) { src = A + (size_t)(mBase + row) * KDIM + k0 + c * 8; toff = T_A; }
        else        { src = B + (size_t)(nBase + row) * KDIM + k0 + c * 8; toff = T_B; }
        cp16(st + toff + (uint32_t)(row * ROWB + c * 16), src);
    }
}

// Load one B half (4 nj tiles, one ks) into bf[p]
#define LOAD_B(p, ksv, hv) do {                                                   \
    uint32_t r[4];                                                                \
    ldsm4(r, st + T_B + bOff + (uint32_t)(((hv) * 2 + 0) * 16 * ROWB) + (ksv) * 32); \
    bf[p][0][0] = r[0]; bf[p][0][1] = r[1]; bf[p][1][0] = r[2]; bf[p][1][1] = r[3]; \
    ldsm4(r, st + T_B + bOff + (uint32_t)(((hv) * 2 + 1) * 16 * ROWB) + (ksv) * 32); \
    bf[p][2][0] = r[0]; bf[p][2][1] = r[1]; bf[p][3][0] = r[2]; bf[p][3][1] = r[3]; \
} while (0)

__global__ __launch_bounds__(NTHREADS, 2)
void gemm_mma()
{
    extern __shared__ char smem[];
    const int which = blockIdx.z;
    const __half *A, *B;
    float* C;
    if (which == 0) { A = g_h0f; B = g_whf; C = g_gh; }
    else            { A = g_xf;  B = g_wxf; C = g_gx; }

    const int nBase = blockIdx.x * BN;
    const int mBase = blockIdx.y * BM;
    const int tid  = threadIdx.x;
    const int lane = tid & 31;
    const int wid  = tid >> 5;
    const int wm   = wid & 3;      // 4 warps along M
    const int wn   = wid >> 2;     // 2 warps along N
    uint32_t sb = smem_u32(smem);

    const uint32_t aOff = (uint32_t)((wm * 32 + (lane & 15)) * ROWB + (lane >> 4) * 16);
    const uint32_t bRow = (uint32_t)(wn * 64 + ((lane >> 4) << 3) + (lane & 7));
    const uint32_t bOff = bRow * ROWB + ((lane >> 3) & 1) * 16;

    float acc[2][8][4];
    #pragma unroll
    for (int mi = 0; mi < 2; mi++)
        #pragma unroll
        for (int ni = 0; ni < 8; ni++)
            #pragma unroll
            for (int q = 0; q < 4; q++)
                acc[mi][ni][q] = 0.0f;

    // Prologue: stage 0
    load_stage(sb, 0, A, B, mBase, nBase, 0, tid);
    asm volatile("cp.async.commit_group;" ::: "memory");

    for (int k = 0; k < KTILES; k++) {
        // Issue loads for stage k+1 (its buffer was consumed in iter k-1,
        // whose compute finished before that iteration's trailing barrier).
        if (k + 1 < KTILES) {
            load_stage(sb, (k + 1) & 1, A, B, mBase, nBase, (k + 1) * BK, tid);
            asm volatile("cp.async.commit_group;" ::: "memory");
            asm volatile("cp.async.wait_group 1;" ::: "memory");
        } else {
            asm volatile("cp.async.wait_group 0;" ::: "memory");
        }
        __syncthreads();

        uint32_t st = sb + (k & 1) * STAGE;

        // Fragment pipeline over 8 steps: s=(ks<<1)|h.
        // A fragments double-buffered across ks; B double-buffered per step.
        uint32_t af[2][2][4];     // [ks parity][mi][4]
        uint32_t bf[2][4][2];     // [step parity][nj][2]

        ldsm4(af[0][0], st + T_A + aOff);
        ldsm4(af[0][1], st + T_A + aOff + 16 * ROWB);
        LOAD_B(0, 0, 0);

        #pragma unroll
        for (int s = 0; s < 8; s++) {
            const int ks = s >> 1;
            const int h  = s & 1;
            const int cur = s & 1;
            if (s < 7)
                LOAD_B((s + 1) & 1, (s + 1) >> 1, (s + 1) & 1);
            if (h == 0 && ks < 3) {
                ldsm4(af[(ks + 1) & 1][0], st + T_A + aOff + (ks + 1) * 32);
                ldsm4(af[(ks + 1) & 1][1], st + T_A + aOff + 16 * ROWB + (ks + 1) * 32);
            }
            #pragma unroll
            for (int mi = 0; mi < 2; mi++)
                #pragma unroll
                for (int nj = 0; nj < 4; nj++)
                    mma16816(acc[mi][h * 4 + nj], af[ks & 1][mi], bf[cur][nj]);
        }
        __syncthreads();
    }

    // Write back
    #pragma unroll
    for (int mi = 0; mi < 2; mi++) {
        #pragma unroll
        for (int ni = 0; ni < 8; ni++) {
            int row = mBase + wm * 32 + mi * 16 + (lane >> 2);
            int col = nBase + wn * 64 + ni * 8 + (lane & 3) * 2;
            float2 v0 = make_float2(acc[mi][ni][0], acc[mi][ni][1]);
            float2 v1 = make_float2(acc[mi][ni][2], acc[mi][ni][3]);
            *reinterpret_cast<float2*>(C + (size_t)row * GDIM + col) = v0;
            *reinterpret_cast<float2*>(C + (size_t)(row + 8) * GDIM + col) = v1;
        }
    }
}

// ---------------------------------------------------------------------------
// Fused LSTM epilogue with smem row caching (single global read of gates)
// ---------------------------------------------------------------------------
__device__ __forceinline__ float sigmoidf_fast(float v) {
    return 1.0f / (1.0f + __expf(-v));
}
__device__ __forceinline__ float tanhf_fast(float v) {
    float e = __expf(2.0f * fminf(fmaxf(v, -15.0f), 15.0f));
    return (e - 1.0f) / (e + 1.0f);
}

__device__ __forceinline__ float4 block_reduce4(float4 v) {
    __shared__ float4 sh[8];
    const int lane = threadIdx.x & 31;
    const int wid  = threadIdx.x >> 5;
    __syncthreads();
    #pragma unroll
    for (int o = 16; o > 0; o >>= 1) {
        v.x += __shfl_down_sync(0xffffffffu, v.x, o);
        v.y += __shfl_down_sync(0xffffffffu, v.y, o);
        v.z += __shfl_down_sync(0xffffffffu, v.z, o);
        v.w += __shfl_down_sync(0xffffffffu, v.w, o);
    }
    if (lane == 0) sh[wid] = v;
    __syncthreads();
    if (wid == 0) {
        v = (lane < 8) ? sh[lane] : make_float4(0.f, 0.f, 0.f, 0.f);
        #pragma unroll
        for (int o = 4; o > 0; o >>= 1) {
            v.x += __shfl_down_sync(0xffffffffu, v.x, o);
            v.y += __shfl_down_sync(0xffffffffu, v.y, o);
            v.z += __shfl_down_sync(0xffffffffu, v.z, o);
            v.w += __shfl_down_sync(0xffffffffu, v.w, o);
        }
        if (lane == 0) sh[0] = v;
    }
    __syncthreads();
    return sh[0];
}

__global__ __launch_bounds__(256, 4)
void epilogue_kernel(const float* __restrict__ c0,
                     const float* __restrict__ bias,
                     const float* __restrict__ ln1g, const float* __restrict__ ln1b,
                     const float* __restrict__ ln2g, const float* __restrict__ ln2b,
                     const float* __restrict__ ln3g, const float* __restrict__ ln3b,
                     float* __restrict__ h1, float* __restrict__ c1)
{
    __shared__ float sgh[GDIM];
    __shared__ float sgx[GDIM];

    const int b   = blockIdx.x;
    const int tid = threadIdx.x;
    const float4* __restrict__ ghr = reinterpret_cast<const float4*>(g_gh + (size_t)b * GDIM);
    const float4* __restrict__ gxr = reinterpret_cast<const float4*>(g_gx + (size_t)b * GDIM);

    const float EPS = 1e-5f;

    float4 st = make_float4(0.f, 0.f, 0.f, 0.f);
    #pragma unroll
    for (int it = 0; it < 4; it++) {
        int i = tid + it * 256;
        float4 v = ghr[i];
        float4 w = gxr[i];
        *reinterpret_cast<float4*>(&sgh[i * 4]) = v;
        *reinterpret_cast<float4*>(&sgx[i * 4]) = w;
        st.x += v.x + v.y + v.z + v.w;
        st.y += v.x * v.x + v.y * v.y + v.z * v.z + v.w * v.w;
        st.z += w.x + w.y + w.z + w.w;
        st.w += w.x * w.x + w.y * w.y + w.z * w.z + w.w * w.w;
    }
    st = block_reduce4(st);
    const float inv4h = 1.0f / (float)GDIM;
    float mu1 = st.x * inv4h;
    float rs1 = rsqrtf(fmaxf(st.y * inv4h - mu1 * mu1, 0.f) + EPS);
    float mu2 = st.z * inv4h;
    float rs2 = rsqrtf(fmaxf(st.w * inv4h - mu2 * mu2, 0.f) + EPS);

    float c1v[4];
    float ogv[4];
    float4 st3 = make_float4(0.f, 0.f, 0.f, 0.f);
    #pragma unroll
    for (int it = 0; it < 4; it++) {
        int j = tid + it * 256;
        int jf = j, ji = j + 1024, jo = j + 2048, jc = j + 3072;
        float gf = (sgh[jf] - mu1) * rs1 * ln1g[jf] + ln1b[jf]
                 + (sgx[jf] - mu2) * rs2 * ln2g[jf] + ln2b[jf] + bias[jf];
        float gi = (sgh[ji] - mu1) * rs1 * ln1g[ji] + ln1b[ji]
                 + (sgx[ji] - mu2) * rs2 * ln2g[ji] + ln2b[ji] + bias[ji];
        float go = (sgh[jo] - mu1) * rs1 * ln1g[jo] + ln1b[jo]
                 + (sgx[jo] - mu2) * rs2 * ln2g[jo] + ln2b[jo] + bias[jo];
        float gc = (sgh[jc] - mu1) * rs1 * ln1g[jc] + ln1b[jc]
                 + (sgx[jc] - mu2) * rs2 * ln2g[jc] + ln2b[jc] + bias[jc];

        float cv = sigmoidf_fast(gf) * c0[(size_t)b * 1024 + j]
                 + sigmoidf_fast(gi) * tanhf_fast(gc);
        c1v[it] = cv;
        ogv[it] = go;
        st3.x += cv;
        st3.y += cv * cv;
        c1[(size_t)b * 1024 + j] = cv;
    }
    st3 = block_reduce4(st3);
    const float invh = 1.0f / 1024.0f;
    float mu3 = st3.x * invh;
    float rs3 = rsqrtf(fmaxf(st3.y * invh - mu3 * mu3, 0.f) + EPS);

    #pragma unroll
    for (int it = 0; it < 4; it++) {
        int j = tid + it * 256;
        float lnc = (c1v[it] - mu3) * rs3 * ln3g[j] + ln3b[j];
        h1[(size_t)b * 1024 + j] = sigmoidf_fast(ogv[it]) * tanhf_fast(lnc);
    }
}

// ---------------------------------------------------------------------------
// Launch: converts -> 2 GEMMs (one grid, z=2) -> fused epilogue
// ---------------------------------------------------------------------------
extern "C" void kernel_launch(void* const* d_in, const int* in_sizes, int n_in,
                              void* d_out, int out_size)
{
    const float* x    = (const float*)d_in[0];
    const float* h0   = (const float*)d_in[1];
    const float* c0   = (const float*)d_in[2];
    const float* Wh   = (const float*)d_in[3];
    const float* Wx   = (const float*)d_in[4];
    const float* bias = (const float*)d_in[5];
    const float* ln1g = (const float*)d_in[6];
    const float* ln1b = (const float*)d_in[7];
    const float* ln2g = (const float*)d_in[8];
    const float* ln2b = (const float*)d_in[9];
    const float* ln3g = (const float*)d_in[10];
    const float* ln3b = (const float*)d_in[11];

    float* out = (float*)d_out;
    float* h1 = out;
    float* c1 = out + (size_t)BATCH * KDIM;

    cudaFuncSetAttribute(gemm_mma, cudaFuncAttributeMaxDynamicSharedMemorySize,
                         SMEM_TOTAL);

    // fp16 conversions
    {
        int blocks = (int)(((size_t)BATCH * KDIM / 4) / 256);
        convert_act<<<blocks, 256>>>(h0, 0);
        convert_act<<<blocks, 256>>>(x,  1);
        dim3 tg(GDIM / 64, KDIM / 64);
        convert_wt<<<tg, 256>>>(Wh, 0);
        convert_wt<<<tg, 256>>>(Wx, 1);
    }

    // Tensor-core GEMMs: grid (N tiles, M tiles, which)
    dim3 grid(GDIM / BN, BATCH / BM, 2);
    gemm_mma<<<grid, NTHREADS, SMEM_TOTAL>>>();

    epilogue_kernel<<<BATCH, 256>>>(c0, bias, ln1g, ln1b, ln2g, ln2b,
                                    ln3g, ln3b, h1, c1);
}

// round 8
// speedup vs baseline: 6.4811x; 1.0110x over previous
#include <cuda_runtime.h>
#include <cuda_fp16.h>
#include <math.h>
#include <stdint.h>

// Problem dims (fixed): B=8192, K(=D=H)=1024, 4H=4096
#define BATCH 8192
#define KDIM  1024
#define GDIM  4096

// ---------------------------------------------------------------------------
// Device-global scratch (allocation-free rule)
// ---------------------------------------------------------------------------
__device__ __half g_gh[(size_t)BATCH * GDIM];   // h0 @ Wh (fp16 storage)
__device__ __half g_gx[(size_t)BATCH * GDIM];   // x  @ Wx (fp16 storage)

// fp16 operands. A-side: [M][K] row-major (K-major).
__device__ __half g_h0f[(size_t)BATCH * KDIM];
__device__ __half g_xf [(size_t)BATCH * KDIM];
// B-side: transposed weights [N=4096][K=1024] (K-major rows)
__device__ __half g_whf[(size_t)GDIM * KDIM];
__device__ __half g_wxf[(size_t)GDIM * KDIM];

// ---------------------------------------------------------------------------
// Conversion kernels
// ---------------------------------------------------------------------------
__global__ __launch_bounds__(256)
void convert_act(const float* __restrict__ src, int which)
{
    __half* dst = which ? g_xf : g_h0f;
    size_t i = ((size_t)blockIdx.x * 256 + threadIdx.x) * 4;
    float4 v = *reinterpret_cast<const float4*>(src + i);
    __half2 h0 = __floats2half2_rn(v.x, v.y);
    __half2 h1 = __floats2half2_rn(v.z, v.w);
    *reinterpret_cast<__half2*>(dst + i)     = h0;
    *reinterpret_cast<__half2*>(dst + i + 2) = h1;
}

// Transpose: W[K=1024][N=4096] -> Wt [N][K] fp16. 64x64 tiles, 256 threads.
__global__ __launch_bounds__(256)
void convert_wt(const float* __restrict__ W, int which)
{
    __half* T = which ? g_wxf : g_whf;
    __shared__ float tile[64][65];
    const int tid = threadIdx.x;
    const int n0 = blockIdx.x * 64;
    const int k0 = blockIdx.y * 64;
    #pragma unroll
    for (int it = 0; it < 4; it++) {
        int i = tid + it * 256;
        int r = i >> 4;
        int c4 = i & 15;
        float4 v = *reinterpret_cast<const float4*>(
            &W[(size_t)(k0 + r) * GDIM + n0 + c4 * 4]);
        tile[r][c4 * 4 + 0] = v.x;
        tile[r][c4 * 4 + 1] = v.y;
        tile[r][c4 * 4 + 2] = v.z;
        tile[r][c4 * 4 + 3] = v.w;
    }
    __syncthreads();
    #pragma unroll
    for (int it = 0; it < 8; it++) {
        int i = tid + it * 256;
        int n = i >> 5;
        int k2 = i & 31;
        __half2 hv = __floats2half2_rn(tile[k2 * 2][n], tile[k2 * 2 + 1][n]);
        *reinterpret_cast<__half2*>(&T[(size_t)(n0 + n) * KDIM + k0 + k2 * 2]) = hv;
    }
}

// ---------------------------------------------------------------------------
// mma.sync fp16 single-pass GEMM (fp32 accumulate, fp16 output):  C = A * B^T
// CTA tile 128x128, BK=64, 3-stage cp.async pipeline (ONE barrier per iter),
// 8 warps (warp 32x64), 2 CTAs/SM.
// ---------------------------------------------------------------------------
#define BM 128
#define BN 128
#define BK 64
#define KTILES (KDIM / BK)      // 16
#define NTHREADS 256
#define NSTAGES 3

#define ROWB 144                 // bytes per smem row (64 fp16 + 16 pad)
#define T_A 0
#define T_B (128 * ROWB)         // 18432
#define STAGE (2 * 128 * ROWB)   // 36864
#define SMEM_TOTAL (NSTAGES * STAGE)   // 110592 -> 2 CTAs/SM (221 KB <= 228 KB)

__device__ __forceinline__ uint32_t smem_u32(const void* p) {
    return (uint32_t)__cvta_generic_to_shared(p);
}
__device__ __forceinline__ void cp16(uint32_t dst, const void* src) {
    asm volatile("cp.async.cg.shared.global [%0], [%1], 16;\n" :: "r"(dst), "l"(src));
}
__device__ __forceinline__ void ldsm4(uint32_t* r, uint32_t addr) {
    asm volatile("ldmatrix.sync.aligned.m8n8.x4.shared.b16 {%0,%1,%2,%3}, [%4];\n"
                 : "=r"(r[0]), "=r"(r[1]), "=r"(r[2]), "=r"(r[3]) : "r"(addr));
}
__device__ __forceinline__ void mma16816(float* d, const uint32_t* a, const uint32_t* b) {
    asm volatile(
        "mma.sync.aligned.m16n8k16.row.col.f32.f16.f16.f32 "
        "{%0,%1,%2,%3}, {%4,%5,%6,%7}, {%8,%9}, {%0,%1,%2,%3};\n"
        : "+f"(d[0]), "+f"(d[1]), "+f"(d[2]), "+f"(d[3])
        : "r"(a[0]), "r"(a[1]), "r"(a[2]), "r"(a[3]), "r"(b[0]), "r"(b[1]));
}

__device__ __forceinline__ void load_stage(uint32_t sb, int buf,
                                           const __half* A, const __half* B,
                                           int mBase, int nBase, int k0, int tid)
{
    uint32_t st = sb + buf * STAGE;
    #pragma unroll
    for (int it = 0; it < 2048 / NTHREADS; it++) {
        int i = tid + it * NTHREADS;
        int t = i >> 10;          // 0:A 1:B
        int j = i & 1023;
        int row = j >> 3;
        int c = j & 7;
        const __half* src;
        uint32_t toff;
        if (t == 0) { src = A + (size_t)(mBase + row) * KDIM + k0 + c * 8; toff = T_A; }
        else        { src = B + (size_t)(nBase + row) * KDIM + k0 + c * 8; toff = T_B; }
        cp16(st + toff + (uint32_t)(row * ROWB + c * 16), src);
    }
}

#define LOAD_B(p, ksv, hv) do {                                                   \
    uint32_t r[4];                                                                \
    ldsm4(r, st + T_B + bOff + (uint32_t)(((hv) * 2 + 0) * 16 * ROWB) + (ksv) * 32); \
    bf[p][0][0] = r[0]; bf[p][0][1] = r[1]; bf[p][1][0] = r[2]; bf[p][1][1] = r[3]; \
    ldsm4(r, st + T_B + bOff + (uint32_t)(((hv) * 2 + 1) * 16 * ROWB) + (ksv) * 32); \
    bf[p][2][0] = r[0]; bf[p][2][1] = r[1]; bf[p][3][0] = r[2]; bf[p][3][1] = r[3]; \
} while (0)

__global__ __launch_bounds__(NTHREADS, 2)
void gemm_mma()
{
    extern __shared__ char smem[];
    const int which = blockIdx.z;
    const __half *A, *B;
    __half* C;
    if (which == 0) { A = g_h0f; B = g_whf; C = g_gh; }
    else            { A = g_xf;  B = g_wxf; C = g_gx; }

    const int nBase = blockIdx.x * BN;
    const int mBase = blockIdx.y * BM;
    const int tid  = threadIdx.x;
    const int lane = tid & 31;
    const int wid  = tid >> 5;
    const int wm   = wid & 3;
    const int wn   = wid >> 2;
    uint32_t sb = smem_u32(smem);

    const uint32_t aOff = (uint32_t)((wm * 32 + (lane & 15)) * ROWB + (lane >> 4) * 16);
    const uint32_t bRow = (uint32_t)(wn * 64 + ((lane >> 4) << 3) + (lane & 7));
    const uint32_t bOff = bRow * ROWB + ((lane >> 3) & 1) * 16;

    float acc[2][8][4];
    #pragma unroll
    for (int mi = 0; mi < 2; mi++)
        #pragma unroll
        for (int ni = 0; ni < 8; ni++)
            #pragma unroll
            for (int q = 0; q < 4; q++)
                acc[mi][ni][q] = 0.0f;

    // Prologue: stages 0, 1
    load_stage(sb, 0, A, B, mBase, nBase, 0,  tid);
    asm volatile("cp.async.commit_group;" ::: "memory");
    load_stage(sb, 1, A, B, mBase, nBase, BK, tid);
    asm volatile("cp.async.commit_group;" ::: "memory");

    // Stage buffer index k % 3
    int buf = 0;
    for (int k = 0; k < KTILES; k++) {
        // Wait for group k (allow group k+1 to stay in flight)
        if (k < KTILES - 1)
            asm volatile("cp.async.wait_group 1;" ::: "memory");
        else
            asm volatile("cp.async.wait_group 0;" ::: "memory");
        __syncthreads();   // all warps done with buffer (k+2)%3 (iter k-1)

        // Issue loads for stage k+2 into the buffer freed by iter k-1
        if (k + 2 < KTILES) {
            int nb = buf + 2; if (nb >= 3) nb -= 3;
            load_stage(sb, nb, A, B, mBase, nBase, (k + 2) * BK, tid);
            asm volatile("cp.async.commit_group;" ::: "memory");
        }

        uint32_t st = sb + buf * STAGE;

        uint32_t af[2][2][4];
        uint32_t bf[2][4][2];

        ldsm4(af[0][0], st + T_A + aOff);
        ldsm4(af[0][1], st + T_A + aOff + 16 * ROWB);
        LOAD_B(0, 0, 0);

        #pragma unroll
        for (int s = 0; s < 8; s++) {
            const int ks = s >> 1;
            const int h  = s & 1;
            const int cur = s & 1;
            if (s < 7)
                LOAD_B((s + 1) & 1, (s + 1) >> 1, (s + 1) & 1);
            if (h == 0 && ks < 3) {
                ldsm4(af[(ks + 1) & 1][0], st + T_A + aOff + (ks + 1) * 32);
                ldsm4(af[(ks + 1) & 1][1], st + T_A + aOff + 16 * ROWB + (ks + 1) * 32);
            }
            #pragma unroll
            for (int mi = 0; mi < 2; mi++)
                #pragma unroll
                for (int nj = 0; nj < 4; nj++)
                    mma16816(acc[mi][h * 4 + nj], af[ks & 1][mi], bf[cur][nj]);
        }

        buf++; if (buf >= 3) buf -= 3;
    }

    // Write back as fp16 (half2 stores)
    #pragma unroll
    for (int mi = 0; mi < 2; mi++) {
        #pragma unroll
        for (int ni = 0; ni < 8; ni++) {
            int row = mBase + wm * 32 + mi * 16 + (lane >> 2);
            int col = nBase + wn * 64 + ni * 8 + (lane & 3) * 2;
            __half2 v0 = __floats2half2_rn(acc[mi][ni][0], acc[mi][ni][1]);
            __half2 v1 = __floats2half2_rn(acc[mi][ni][2], acc[mi][ni][3]);
            *reinterpret_cast<__half2*>(C + (size_t)row * GDIM + col) = v0;
            *reinterpret_cast<__half2*>(C + (size_t)(row + 8) * GDIM + col) = v1;
        }
    }
}

// ---------------------------------------------------------------------------
// Fused LSTM epilogue: fp16 gate rows cached in smem, single global read
// ---------------------------------------------------------------------------
__device__ __forceinline__ float sigmoidf_fast(float v) {
    return 1.0f / (1.0f + __expf(-v));
}
__device__ __forceinline__ float tanhf_fast(float v) {
    float e = __expf(2.0f * fminf(fmaxf(v, -15.0f), 15.0f));
    return (e - 1.0f) / (e + 1.0f);
}

__device__ __forceinline__ float4 block_reduce4(float4 v) {
    __shared__ float4 sh[8];
    const int lane = threadIdx.x & 31;
    const int wid  = threadIdx.x >> 5;
    __syncthreads();
    #pragma unroll
    for (int o = 16; o > 0; o >>= 1) {
        v.x += __shfl_down_sync(0xffffffffu, v.x, o);
        v.y += __shfl_down_sync(0xffffffffu, v.y, o);
        v.z += __shfl_down_sync(0xffffffffu, v.z, o);
        v.w += __shfl_down_sync(0xffffffffu, v.w, o);
    }
    if (lane == 0) sh[wid] = v;
    __syncthreads();
    if (wid == 0) {
        v = (lane < 8) ? sh[lane] : make_float4(0.f, 0.f, 0.f, 0.f);
        #pragma unroll
        for (int o = 4; o > 0; o >>= 1) {
            v.x += __shfl_down_sync(0xffffffffu, v.x, o);
            v.y += __shfl_down_sync(0xffffffffu, v.y, o);
            v.z += __shfl_down_sync(0xffffffffu, v.z, o);
            v.w += __shfl_down_sync(0xffffffffu, v.w, o);
        }
        if (lane == 0) sh[0] = v;
    }
    __syncthreads();
    return sh[0];
}

__global__ __launch_bounds__(256, 4)
void epilogue_kernel(const float* __restrict__ c0,
                     const float* __restrict__ bias,
                     const float* __restrict__ ln1g, const float* __restrict__ ln1b,
                     const float* __restrict__ ln2g, const float* __restrict__ ln2b,
                     const float* __restrict__ ln3g, const float* __restrict__ ln3b,
                     float* __restrict__ h1, float* __restrict__ c1)
{
    __shared__ __half sgh[GDIM];
    __shared__ __half sgx[GDIM];

    const int b   = blockIdx.x;
    const int tid = threadIdx.x;
    const uint4* __restrict__ ghr = reinterpret_cast<const uint4*>(g_gh + (size_t)b * GDIM);
    const uint4* __restrict__ gxr = reinterpret_cast<const uint4*>(g_gx + (size_t)b * GDIM);

    const float EPS = 1e-5f;

    // Single global read (8 halves per uint4), cache + stats
    float4 st = make_float4(0.f, 0.f, 0.f, 0.f);
    #pragma unroll
    for (int it = 0; it < 2; it++) {
        int i = tid + it * 256;      // uint4 index (512 total per row)
        uint4 v = ghr[i];
        uint4 w = gxr[i];
        *reinterpret_cast<uint4*>(&sgh[i * 8]) = v;
        *reinterpret_cast<uint4*>(&sgx[i * 8]) = w;
        const __half2* vh = reinterpret_cast<const __half2*>(&v);
        const __half2* wh = reinterpret_cast<const __half2*>(&w);
        #pragma unroll
        for (int q = 0; q < 4; q++) {
            float2 a = __half22float2(vh[q]);
            float2 bb = __half22float2(wh[q]);
            st.x += a.x + a.y;
            st.y += a.x * a.x + a.y * a.y;
            st.z += bb.x + bb.y;
            st.w += bb.x * bb.x + bb.y * bb.y;
        }
    }
    st = block_reduce4(st);   // leading barrier also publishes sgh/sgx
    const float inv4h = 1.0f / (float)GDIM;
    float mu1 = st.x * inv4h;
    float rs1 = rsqrtf(fmaxf(st.y * inv4h - mu1 * mu1, 0.f) + EPS);
    float mu2 = st.z * inv4h;
    float rs2 = rsqrtf(fmaxf(st.w * inv4h - mu2 * mu2, 0.f) + EPS);

    float c1v[4];
    float ogv[4];
    float4 st3 = make_float4(0.f, 0.f, 0.f, 0.f);
    #pragma unroll
    for (int it = 0; it < 4; it++) {
        int j = tid + it * 256;
        int jf = j, ji = j + 1024, jo = j + 2048, jc = j + 3072;
        float gf = (__half2float(sgh[jf]) - mu1) * rs1 * ln1g[jf] + ln1b[jf]
                 + (__half2float(sgx[jf]) - mu2) * rs2 * ln2g[jf] + ln2b[jf] + bias[jf];
        float gi = (__half2float(sgh[ji]) - mu1) * rs1 * ln1g[ji] + ln1b[ji]
                 + (__half2float(sgx[ji]) - mu2) * rs2 * ln2g[ji] + ln2b[ji] + bias[ji];
        float go = (__half2float(sgh[jo]) - mu1) * rs1 * ln1g[jo] + ln1b[jo]
                 + (__half2float(sgx[jo]) - mu2) * rs2 * ln2g[jo] + ln2b[jo] + bias[jo];
        float gc = (__half2float(sgh[jc]) - mu1) * rs1 * ln1g[jc] + ln1b[jc]
                 + (__half2float(sgx[jc]) - mu2) * rs2 * ln2g[jc] + ln2b[jc] + bias[jc];

        float cv = sigmoidf_fast(gf) * c0[(size_t)b * 1024 + j]
                 + sigmoidf_fast(gi) * tanhf_fast(gc);
        c1v[it] = cv;
        ogv[it] = go;
        st3.x += cv;
        st3.y += cv * cv;
        c1[(size_t)b * 1024 + j] = cv;
    }
    st3 = block_reduce4(st3);
    const float invh = 1.0f / 1024.0f;
    float mu3 = st3.x * invh;
    float rs3 = rsqrtf(fmaxf(st3.y * invh - mu3 * mu3, 0.f) + EPS);

    #pragma unroll
    for (int it = 0; it < 4; it++) {
        int j = tid + it * 256;
        float lnc = (c1v[it] - mu3) * rs3 * ln3g[j] + ln3b[j];
        h1[(size_t)b * 1024 + j] = sigmoidf_fast(ogv[it]) * tanhf_fast(lnc);
    }
}

// ---------------------------------------------------------------------------
// Launch: converts -> 2 GEMMs (one grid, z=2) -> fused epilogue
// ---------------------------------------------------------------------------
extern "C" void kernel_launch(void* const* d_in, const int* in_sizes, int n_in,
                              void* d_out, int out_size)
{
    const float* x    = (const float*)d_in[0];
    const float* h0   = (const float*)d_in[1];
    const float* c0   = (const float*)d_in[2];
    const float* Wh   = (const float*)d_in[3];
    const float* Wx   = (const float*)d_in[4];
    const float* bias = (const float*)d_in[5];
    const float* ln1g = (const float*)d_in[6];
    const float* ln1b = (const float*)d_in[7];
    const float* ln2g = (const float*)d_in[8];
    const float* ln2b = (const float*)d_in[9];
    const float* ln3g = (const float*)d_in[10];
    const float* ln3b = (const float*)d_in[11];

    float* out = (float*)d_out;
    float* h1 = out;
    float* c1 = out + (size_t)BATCH * KDIM;

    cudaFuncSetAttribute(gemm_mma, cudaFuncAttributeMaxDynamicSharedMemorySize,
                         SMEM_TOTAL);

    // fp16 conversions
    {
        int blocks = (int)(((size_t)BATCH * KDIM / 4) / 256);
        convert_act<<<blocks, 256>>>(h0, 0);
        convert_act<<<blocks, 256>>>(x,  1);
        dim3 tg(GDIM / 64, KDIM / 64);
        convert_wt<<<tg, 256>>>(Wh, 0);
        convert_wt<<<tg, 256>>>(Wx, 1);
    }

    // Tensor-core GEMMs: grid (N tiles, M tiles, which)
    dim3 grid(GDIM / BN, BATCH / BM, 2);
    gemm_mma<<<grid, NTHREADS, SMEM_TOTAL>>>();

    epilogue_kernel<<<BATCH, 256>>>(c0, bias, ln1g, ln1b, ln2g, ln2b,
                                    ln3g, ln3b, h1, c1);
}